// round 4
// baseline (speedup 1.0000x reference)
#include <cuda_runtime.h>
#include <math.h>

#define BB      32768
#define NB      16          // batches per CTA
#define NT      512         // threads per CTA (16 warps, warp == batch)
#define SCALE_ATT 0.125f
#define LN_EPS  1e-5f
#define STR     68          // padded activation row stride (68 % 32 == 4 -> conflict-free)

// Output packing offsets (flat concat of return tuple, C-order)
#define OFF_COLOR 0
#define OFF_SIGMA (3 * BB)
#define OFF_OUT   (OFF_SIGMA + BB)
#define OFF_ATTN  (OFF_OUT + (size_t)BB * 512)

// Shared memory layout (floats)
#define SX_OFF   0              // [128][68] activations
#define ST0_OFF  8704           // [128][68] Q / ctx / ffn-h1 / Kc
#define ST1_OFF  17408          // [128][68] K / Y / Vc
#define ST2_OFF  26112          // [128][68] V / Qc rows
#define SW_OFF   34816          // 16384 : four 4096-float weight slots
#define SP_OFF   51200          // [16][64] probs
#define SQI_OFF  52224          // [16][64] query in
#define SCA_OFF  53248          // [16][64] cross ctx row
#define SMEM_FLOATS 54272       // 217088 bytes

typedef unsigned long long ull;

__device__ __forceinline__ ull pk2(float lo, float hi) {
    ull r;
    asm("mov.b64 %0, {%1, %2};" : "=l"(r) : "r"(__float_as_uint(lo)), "r"(__float_as_uint(hi)));
    return r;
}
__device__ __forceinline__ void fma2(ull &acc, ull a, ull b) {
    asm("fma.rn.f32x2 %0, %1, %2, %0;" : "+l"(acc) : "l"(a), "l"(b));
}
__device__ __forceinline__ float2 upk(ull v) {
    unsigned int lo, hi;
    asm("mov.b64 {%0, %1}, %2;" : "=r"(lo), "=r"(hi) : "l"(v));
    return make_float2(__uint_as_float(lo), __uint_as_float(hi));
}

// ---- cooperative copiers ----
__device__ __forceinline__ void cp_f4(float* __restrict__ dst, const float* __restrict__ src,
                                      int n4, int tid) {
    for (int i = tid; i < n4; i += NT)
        reinterpret_cast<float4*>(dst)[i] = reinterpret_cast<const float4*>(src)[i];
}
// copy a [64][64] head slice out of a [64][256] row-major matrix (src at col h*64)
__device__ __forceinline__ void cp_slice(float* __restrict__ dst, const float* __restrict__ src,
                                         int tid) {
    for (int i = tid; i < 64 * 16; i += NT) {
        int r = i >> 4, c = i & 15;
        reinterpret_cast<float4*>(dst)[i] =
            reinterpret_cast<const float4*>(src + r * 256)[c];
    }
}

// ---- GEMM core: Y[128][64] (+)= X[128][K] @ W[K][64] ----
// thread tile: 2 rows x 8 cols, k-vectorized float4 loads, packed FFMA2
template<int K, int LDX>
__device__ __forceinline__ void gemm_acc8(const float* __restrict__ X,
                                          const float* __restrict__ W,
                                          ull a0[4], ull a1[4], int c0, int rb) {
#pragma unroll 4
    for (int k = 0; k < K; k += 4) {
        float4 x0 = *reinterpret_cast<const float4*>(X + rb * LDX + k);
        float4 x1 = *reinterpret_cast<const float4*>(X + (rb + 1) * LDX + k);
#pragma unroll
        for (int kk = 0; kk < 4; ++kk) {
            float4 wa = *reinterpret_cast<const float4*>(W + (k + kk) * 64 + c0);
            float4 wb = *reinterpret_cast<const float4*>(W + (k + kk) * 64 + c0 + 4);
            ull w01 = pk2(wa.x, wa.y), w23 = pk2(wa.z, wa.w);
            ull w45 = pk2(wb.x, wb.y), w67 = pk2(wb.z, wb.w);
            float xs0 = reinterpret_cast<const float*>(&x0)[kk];
            float xs1 = reinterpret_cast<const float*>(&x1)[kk];
            ull xx0 = pk2(xs0, xs0);
            ull xx1 = pk2(xs1, xs1);
            fma2(a0[0], w01, xx0); fma2(a0[1], w23, xx0);
            fma2(a0[2], w45, xx0); fma2(a0[3], w67, xx0);
            fma2(a1[0], w01, xx1); fma2(a1[1], w23, xx1);
            fma2(a1[2], w45, xx1); fma2(a1[3], w67, xx1);
        }
    }
}

template<bool RELU>
__device__ __forceinline__ void emit_row(float* __restrict__ dst, const ull a[4],
                                         float4 bA, float4 bB) {
    float2 v0 = upk(a[0]), v1 = upk(a[1]), v2 = upk(a[2]), v3 = upk(a[3]);
    float o0 = v0.x + bA.x, o1 = v0.y + bA.y, o2 = v1.x + bA.z, o3 = v1.y + bA.w;
    float o4 = v2.x + bB.x, o5 = v2.y + bB.y, o6 = v3.x + bB.z, o7 = v3.y + bB.w;
    if (RELU) {
        o0 = fmaxf(o0, 0.f); o1 = fmaxf(o1, 0.f); o2 = fmaxf(o2, 0.f); o3 = fmaxf(o3, 0.f);
        o4 = fmaxf(o4, 0.f); o5 = fmaxf(o5, 0.f); o6 = fmaxf(o6, 0.f); o7 = fmaxf(o7, 0.f);
    }
    *reinterpret_cast<float4*>(dst)     = make_float4(o0, o1, o2, o3);
    *reinterpret_cast<float4*>(dst + 4) = make_float4(o4, o5, o6, o7);
}

template<int K, int LDX, bool RELU>
__device__ __forceinline__ void gemm_block8(const float* __restrict__ X,
                                            const float* __restrict__ W,
                                            const float* __restrict__ bias,
                                            float* __restrict__ Y, int tid) {
    const int c0 = (tid & 7) * 8;
    const int rb = (tid >> 3) * 2;
    ull a0[4] = {0, 0, 0, 0};
    ull a1[4] = {0, 0, 0, 0};
    gemm_acc8<K, LDX>(X, W, a0, a1, c0, rb);
    float4 bA = *reinterpret_cast<const float4*>(bias + c0);
    float4 bB = *reinterpret_cast<const float4*>(bias + c0 + 4);
    emit_row<RELU>(Y + rb * STR + c0, a0, bA, bB);
    emit_row<RELU>(Y + (rb + 1) * STR + c0, a1, bA, bB);
}

// residual + LayerNorm: Xs[r] = LN(Yd[r] + Xs[r]); warp w rows w*8..w*8+7, stride STR
__device__ __forceinline__ void ln_block(const float* __restrict__ Yd, float* __restrict__ Xs,
                                         const float* __restrict__ g, const float* __restrict__ be,
                                         int w, int l) {
    float g0 = g[l], g1v = g[l + 32], e0 = be[l], e1v = be[l + 32];
#pragma unroll
    for (int i = 0; i < 8; ++i) {
        int r = w * 8 + i;
        float v0 = Yd[r * STR + l]      + Xs[r * STR + l];
        float v1 = Yd[r * STR + 32 + l] + Xs[r * STR + 32 + l];
        float s = v0 + v1;
#pragma unroll
        for (int o = 16; o >= 1; o >>= 1) s += __shfl_xor_sync(0xffffffffu, s, o);
        float m = s * (1.f / 64.f);
        float d0 = v0 - m, d1 = v1 - m;
        float q = d0 * d0 + d1 * d1;
#pragma unroll
        for (int o = 16; o >= 1; o >>= 1) q += __shfl_xor_sync(0xffffffffu, q, o);
        float inv = rsqrtf(q * (1.f / 64.f) + LN_EPS);
        Xs[r * STR + l]      = d0 * inv * g0 + e0;
        Xs[r * STR + 32 + l] = d1 * inv * g1v + e1v;
    }
}

extern "C" __global__ void __launch_bounds__(NT, 1)
radiance_kernel(const float* __restrict__ query, const float* __restrict__ latent,
                const float* __restrict__ W1, const float* __restrict__ b1,
                const float* __restrict__ Wq, const float* __restrict__ bq,
                const float* __restrict__ Wk, const float* __restrict__ bk,
                const float* __restrict__ Wv, const float* __restrict__ bv,
                const float* __restrict__ Wo, const float* __restrict__ bo,
                const float* __restrict__ fW1, const float* __restrict__ fb1,
                const float* __restrict__ fW2, const float* __restrict__ fb2,
                const float* __restrict__ g1, const float* __restrict__ be1,
                const float* __restrict__ g2, const float* __restrict__ be2,
                const float* __restrict__ cWq, const float* __restrict__ cbq,
                const float* __restrict__ cWk, const float* __restrict__ cbk,
                const float* __restrict__ cWv, const float* __restrict__ cbv,
                const float* __restrict__ cWo, const float* __restrict__ cbo,
                const float* __restrict__ Wc, const float* __restrict__ bc,
                const float* __restrict__ Ws, const float* __restrict__ bs,
                float* __restrict__ out) {
    extern __shared__ float smem[];
    float* SX  = smem + SX_OFF;
    float* ST0 = smem + ST0_OFF;
    float* ST1 = smem + ST1_OFF;
    float* ST2 = smem + ST2_OFF;
    float* SW0 = smem + SW_OFF;
    float* SW1 = SW0 + 4096;
    float* SW2 = SW0 + 8192;
    float* SW3 = SW0 + 12288;
    float* SP  = smem + SP_OFF;
    float* SQI = smem + SQI_OFF;
    float* SCA = smem + SCA_OFF;

    const int tid = threadIdx.x;
    const int w = tid >> 5;     // warp == local batch (0..15)
    const int l = tid & 31;
    const int b0 = blockIdx.x * NB;
    const int c0 = (tid & 7) * 8;
    const int rb = (tid >> 3) * 2;

    float* attn_out = out + OFF_ATTN;

    // ================= Stage 0: x = relu(latent @ W1 + b1) =================
    {
        ull a0[4] = {0, 0, 0, 0};
        ull a1[4] = {0, 0, 0, 0};
        for (int ch = 0; ch < 4; ++ch) {
            __syncthreads();
            cp_f4(SW0, W1 + ch * 8192, 2048, tid);    // W1 rows ch*128..+128 -> [128][64]
            // latent chunk [128 rows][128 k] -> ST0, stride 132 (conflict-free)
            for (int i = tid; i < 4096; i += NT) {
                int r = i >> 5, j = i & 31;
                *reinterpret_cast<float4*>(ST0 + r * 132 + j * 4) =
                    *reinterpret_cast<const float4*>(latent + (size_t)(b0 * 8 + r) * 512 + ch * 128 + j * 4);
            }
            __syncthreads();
            gemm_acc8<128, 132>(ST0, SW0, a0, a1, c0, rb);
        }
        float4 bA = *reinterpret_cast<const float4*>(b1 + c0);
        float4 bB = *reinterpret_cast<const float4*>(b1 + c0 + 4);
        emit_row<true>(SX + rb * STR + c0, a0, bA, bB);
        emit_row<true>(SX + (rb + 1) * STR + c0, a1, bA, bB);
    }

    // ================= 4 transformer layers =================
    for (int li = 0; li < 4; ++li) {
        const float* Wq_i = Wq + li * 16384;
        const float* Wk_i = Wk + li * 16384;
        const float* Wv_i = Wv + li * 16384;
        const float* Wo_i = Wo + li * 16384;

        ull y0[4] = {0, 0, 0, 0};   // O-projection accumulators (persist over heads)
        ull y1[4] = {0, 0, 0, 0};

        for (int h = 0; h < 4; ++h) {
            __syncthreads();
            cp_slice(SW0, Wq_i + h * 64, tid);
            cp_slice(SW1, Wk_i + h * 64, tid);
            cp_slice(SW2, Wv_i + h * 64, tid);
            cp_f4(SW3, Wo_i + h * 4096, 1024, tid);   // Wo rows h*64..+64
            __syncthreads();
            gemm_block8<64, STR, false>(SX, SW0, bq + li * 256 + h * 64, ST0, tid); // Q
            gemm_block8<64, STR, false>(SX, SW1, bk + li * 256 + h * 64, ST1, tid); // K
            gemm_block8<64, STR, false>(SX, SW2, bv + li * 256 + h * 64, ST2, tid); // V
            __syncthreads();

            // ---- attention per warp (= batch) ----
            {
                const float* qB = ST0 + (w * 8) * STR;
                const float* kB = ST1 + (w * 8) * STR;
                const float* vB = ST2 + (w * 8) * STR;
                const int qi = l >> 3, kj = l & 7;
                float s0 = 0.f, s1 = 0.f;
#pragma unroll
                for (int d4 = 0; d4 < 64; d4 += 4) {
                    float4 kv = *reinterpret_cast<const float4*>(kB + kj * STR + d4);
                    float4 q0 = *reinterpret_cast<const float4*>(qB + qi * STR + d4);
                    float4 q1 = *reinterpret_cast<const float4*>(qB + (qi + 4) * STR + d4);
                    s0 += q0.x * kv.x + q0.y * kv.y + q0.z * kv.z + q0.w * kv.w;
                    s1 += q1.x * kv.x + q1.y * kv.y + q1.z * kv.z + q1.w * kv.w;
                }
                s0 *= SCALE_ATT; s1 *= SCALE_ATT;
                float m0 = s0, m1 = s1;
#pragma unroll
                for (int o = 1; o < 8; o <<= 1) {
                    m0 = fmaxf(m0, __shfl_xor_sync(0xffffffffu, m0, o));
                    m1 = fmaxf(m1, __shfl_xor_sync(0xffffffffu, m1, o));
                }
                float e0 = __expf(s0 - m0), e1 = __expf(s1 - m1);
                float t0 = e0, t1 = e1;
#pragma unroll
                for (int o = 1; o < 8; o <<= 1) {
                    t0 += __shfl_xor_sync(0xffffffffu, t0, o);
                    t1 += __shfl_xor_sync(0xffffffffu, t1, o);
                }
                float p0 = e0 / t0, p1 = e1 / t1;
                SP[w * 64 + l]      = p0;
                SP[w * 64 + 32 + l] = p1;
                size_t ab = (size_t)(b0 + w) * 1024 + li * 256 + h * 64;
                attn_out[ab + l]      = p0;
                attn_out[ab + 32 + l] = p1;
                __syncwarp();
                // ctx = P @ V   (kk-outer: V loads reused across 8 q-rows)
                float acc0[8], acc1[8];
#pragma unroll
                for (int qq = 0; qq < 8; ++qq) { acc0[qq] = 0.f; acc1[qq] = 0.f; }
#pragma unroll
                for (int kk = 0; kk < 8; ++kk) {
                    float v0 = vB[kk * STR + l];
                    float v1 = vB[kk * STR + 32 + l];
#pragma unroll
                    for (int qq = 0; qq < 8; ++qq) {
                        float p = SP[w * 64 + qq * 8 + kk];
                        acc0[qq] += p * v0;
                        acc1[qq] += p * v1;
                    }
                }
#pragma unroll
                for (int qq = 0; qq < 8; ++qq) {       // ctx overwrites own-warp Q rows
                    ST0[(w * 8 + qq) * STR + l]      = acc0[qq];
                    ST0[(w * 8 + qq) * STR + 32 + l] = acc1[qq];
                }
            }
            __syncthreads();
            // accumulate O-projection: Y += ctx_h @ Wo[h]
            gemm_acc8<64, STR>(ST0, SW3, y0, y1, c0, rb);
        } // heads

        // Y + bias -> ST1, then LN into SX
        {
            float4 bA = *reinterpret_cast<const float4*>(bo + li * 64 + c0);
            float4 bB = *reinterpret_cast<const float4*>(bo + li * 64 + c0 + 4);
            emit_row<false>(ST1 + rb * STR + c0, y0, bA, bB);
            emit_row<false>(ST1 + (rb + 1) * STR + c0, y1, bA, bB);
        }
        __syncthreads();
        ln_block(ST1, SX, g1 + li * 64, be1 + li * 64, w, l);
        cp_f4(SW0, fW1 + li * 4096, 1024, tid);
        cp_f4(SW1, fW2 + li * 4096, 1024, tid);
        __syncthreads();
        gemm_block8<64, STR, true>(SX, SW0, fb1 + li * 64, ST0, tid);   // h1 = relu(x@fW1+b)
        __syncthreads();
        gemm_block8<64, STR, false>(ST0, SW1, fb2 + li * 64, ST1, tid); // y2
        __syncthreads();
        ln_block(ST1, SX, g2 + li * 64, be2 + li * 64, w, l);
    } // layers

    // load query rows
    for (int i = tid; i < NB * 64; i += NT)
        SQI[i] = query[(size_t)(b0 + (i >> 6)) * 64 + (i & 63)];

    // ================= Cross attention (ca accumulated in regs) =================
    float ca0 = 0.f, ca1 = 0.f;
    for (int h = 0; h < 4; ++h) {
        __syncthreads();
        cp_slice(SW0, cWq + h * 64, tid);
        cp_slice(SW1, cWk + h * 64, tid);
        cp_slice(SW2, cWv + h * 64, tid);
        cp_f4(SW3, cWo + h * 4096, 1024, tid);
        __syncthreads();
        gemm_block8<64, STR, false>(SX, SW1, cbk + h * 64, ST0, tid); // Kc
        gemm_block8<64, STR, false>(SX, SW2, cbv + h * 64, ST1, tid); // Vc
        // Qc per warp: 1 row x 64 cols
        for (int c = l; c < 64; c += 32) {
            float a = 0.f;
#pragma unroll 8
            for (int k2 = 0; k2 < 64; ++k2) a += SQI[w * 64 + k2] * SW0[k2 * 64 + c];
            ST2[w * STR + c] = a + cbq[h * 64 + c];
        }
        __syncthreads();
        // 1x8 attention per warp
        {
            const int j = l >> 2, part = l & 3;
            const float* qrow = ST2 + w * STR;
            const float* kB = ST0 + (w * 8) * STR;
            float sc = 0.f;
#pragma unroll
            for (int d = part * 16; d < part * 16 + 16; ++d) sc += qrow[d] * kB[j * STR + d];
            sc += __shfl_xor_sync(0xffffffffu, sc, 1);
            sc += __shfl_xor_sync(0xffffffffu, sc, 2);
            sc *= SCALE_ATT;
            if (part == 0) SP[w * 64 + j] = sc;
            __syncwarp();
            float mx = -1e30f;
#pragma unroll
            for (int jj = 0; jj < 8; ++jj) mx = fmaxf(mx, SP[w * 64 + jj]);
            float pe[8], ssum = 0.f;
#pragma unroll
            for (int jj = 0; jj < 8; ++jj) { pe[jj] = __expf(SP[w * 64 + jj] - mx); ssum += pe[jj]; }
            float inv = 1.f / ssum;
            const float* vB = ST1 + (w * 8) * STR;
            for (int c = l; c < 64; c += 32) {
                float a = 0.f;
#pragma unroll
                for (int jj = 0; jj < 8; ++jj) a += pe[jj] * vB[jj * STR + c];
                SCA[w * 64 + c] = a * inv;
            }
            __syncwarp();
            // ca += ctx_h @ cWo[h]
#pragma unroll 8
            for (int k2 = 0; k2 < 64; ++k2) {
                float cv = SCA[w * 64 + k2];
                ca0 += cv * SW3[k2 * 64 + l];
                ca1 += cv * SW3[k2 * 64 + 32 + l];
            }
        }
    }
    // heads: color + sigma
    {
        float a0 = fmaxf(ca0 + cbo[l], 0.f);
        float a1 = fmaxf(ca1 + cbo[l + 32], 0.f);
#pragma unroll
        for (int cc = 0; cc < 3; ++cc) {
            float p = a0 * Wc[l * 3 + cc] + a1 * Wc[(l + 32) * 3 + cc];
#pragma unroll
            for (int o = 16; o >= 1; o >>= 1) p += __shfl_xor_sync(0xffffffffu, p, o);
            if (l == 0) out[OFF_COLOR + (size_t)(b0 + w) * 3 + cc] = p + bc[cc];
        }
        float m0 = -1e30f, m1 = -1e30f;
#pragma unroll
        for (int s2 = 0; s2 < 8; ++s2) {
            m0 = fmaxf(m0, SX[(w * 8 + s2) * STR + l]);
            m1 = fmaxf(m1, SX[(w * 8 + s2) * STR + 32 + l]);
        }
        float p = m0 * Ws[l] + m1 * Ws[l + 32];
#pragma unroll
        for (int o = 16; o >= 1; o >>= 1) p += __shfl_xor_sync(0xffffffffu, p, o);
        if (l == 0) out[OFF_SIGMA + b0 + w] = p + bs[0];
    }
    // final out activations
    for (int i = tid; i < NB * 512; i += NT) {
        int r = i >> 6, c = i & 63;
        out[OFF_OUT + (size_t)b0 * 512 + i] = SX[r * STR + c];
    }
}

extern "C" void kernel_launch(void* const* d_in, const int* in_sizes, int n_in,
                              void* d_out, int out_size) {
    (void)in_sizes; (void)n_in; (void)out_size;
    const float* query  = (const float*)d_in[0];
    const float* latent = (const float*)d_in[1];
    const float* W1  = (const float*)d_in[2];
    const float* b1  = (const float*)d_in[3];
    const float* Wq  = (const float*)d_in[4];
    const float* bq  = (const float*)d_in[5];
    const float* Wk  = (const float*)d_in[6];
    const float* bk  = (const float*)d_in[7];
    const float* Wv  = (const float*)d_in[8];
    const float* bv  = (const float*)d_in[9];
    const float* Wo  = (const float*)d_in[10];
    const float* bo  = (const float*)d_in[11];
    const float* fW1 = (const float*)d_in[12];
    const float* fb1 = (const float*)d_in[13];
    const float* fW2 = (const float*)d_in[14];
    const float* fb2 = (const float*)d_in[15];
    const float* g1  = (const float*)d_in[16];
    const float* be1 = (const float*)d_in[17];
    const float* g2  = (const float*)d_in[18];
    const float* be2 = (const float*)d_in[19];
    const float* cWq = (const float*)d_in[20];
    const float* cbq = (const float*)d_in[21];
    const float* cWk = (const float*)d_in[22];
    const float* cbk = (const float*)d_in[23];
    const float* cWv = (const float*)d_in[24];
    const float* cbv = (const float*)d_in[25];
    const float* cWo = (const float*)d_in[26];
    const float* cbo = (const float*)d_in[27];
    const float* Wc  = (const float*)d_in[28];
    const float* bc  = (const float*)d_in[29];
    const float* Ws  = (const float*)d_in[30];
    const float* bs  = (const float*)d_in[31];
    float* out = (float*)d_out;

    const int smem_bytes = SMEM_FLOATS * sizeof(float);
    cudaFuncSetAttribute(radiance_kernel, cudaFuncAttributeMaxDynamicSharedMemorySize, smem_bytes);

    dim3 grid(BB / NB);
    dim3 block(NT);
    radiance_kernel<<<grid, block, smem_bytes>>>(
        query, latent, W1, b1, Wq, bq, Wk, bk, Wv, bv, Wo, bo,
        fW1, fb1, fW2, fb2, g1, be1, g2, be2,
        cWq, cbq, cWk, cbk, cWv, cbv, cWo, cbo, Wc, bc, Ws, bs, out);
}

// round 9
// speedup vs baseline: 3.7727x; 3.7727x over previous
#include <cuda_runtime.h>
#include <stdint.h>
#include <math.h>

#if defined(__CUDA_ARCH_FEAT_SM103_ALL) || defined(__CUDA_ARCH_FEAT_SM100_ALL) || defined(__CUDA_ARCH_FEAT_SM101_ALL)
#define HAS_TC 1
#else
#define HAS_TC 0
#endif

#define BB 32768
#define LN_EPS 1e-5f
#define SC_ATT 0.125f
#define OFF_SIGMA (3*BB)
#define OFF_OUT (OFF_SIGMA+BB)
#define OFF_ATTN (OFF_OUT+(size_t)BB*512)
#define MMA_GRID 2048

__device__ float g_B[176*4096];   // 88 hi tiles + 88 lo tiles
__device__ int g_ok;

extern "C" __global__ void reset_kernel(){ g_ok = 0; }

__device__ __forceinline__ int axA(int m,int k){return ((k>>5)<<12)|((m>>3)<<8)|((m&7)<<5)|((k&31)^((m&7)<<2));}
__device__ __forceinline__ int axB(int n,int k){return ((k>>5)<<11)|((n>>3)<<8)|((n&7)<<5)|((k&31)^((n&7)<<2));}

__device__ __forceinline__ float tf32r(float x){
    uint32_t u; asm("cvt.rna.tf32.f32 %0,%1;":"=r"(u):"f"(x)); return __uint_as_float(u);
}
__device__ __forceinline__ void split2(float v,float&h,float&l){ h=tf32r(v); l=tf32r(v-h); }

extern "C" __global__ void prep_kernel(const float* W1,const float* Wq,const float* Wk,const float* Wv,
        const float* Wo,const float* fW1,const float* fW2,const float* cWk,const float* cWv){
    int idx=blockIdx.x*256+threadIdx.x;
    if(idx>=88*4096)return;
    int tile=idx>>12,j=idx&4095,n=j>>6,k=j&63;
    float v;
    if(tile<8) v=W1[(tile*64+k)*64+n];
    else if(tile<56){int t=tile-8,lh=t/3,wch=t%3,li=lh>>2,h=lh&3;
        const float* W=(wch==0)?Wq:((wch==1)?Wk:Wv);
        v=W[li*16384+k*256+h*64+n];}
    else if(tile<72){int t=tile-56,li=t>>2,h=t&3; v=Wo[li*16384+(h*64+k)*64+n];}
    else if(tile<80){int t=tile-72,li=t>>1; v=((t&1)?fW2:fW1)[li*4096+k*64+n];}
    else if(tile<84) v=cWk[k*256+(tile-80)*64+n];
    else v=cWv[k*256+(tile-84)*64+n];
    float h,l; split2(v,h,l);
    g_B[((size_t)tile<<12)+axB(n,k)]=h;
    g_B[((size_t)(tile+88)<<12)+axB(n,k)]=l;
}

#if HAS_TC
#define NTM 512
#define IDESC 0x8100910u
// smem float offsets
#define O_XH 0
#define O_XL 8192
#define O_R1 16384
#define O_R2 24576
#define O_R3 32768
#define O_R4 40960
#define O_SP 49152
#define O_QC 50176
#define O_SQI 51200
#define O_CTL 52224
#define SMEMF 52240

__device__ __forceinline__ uint32_t s2u(const void* p){
    uint32_t a; asm("{.reg .u64 t; cvta.to.shared.u64 t,%1; cvt.u32.u64 %0,t;}":"=r"(a):"l"(p)); return a;
}
__device__ __forceinline__ uint32_t elect1(){
    uint32_t r; asm volatile("{.reg .pred p; elect.sync _|p,0xFFFFFFFF; selp.b32 %0,1,0,p;}":"=r"(r)); return r;
}
__device__ __forceinline__ uint64_t sdesc(uint32_t a){
    const uint64_t b=(uint64_t(2)<<61)|(uint64_t(1)<<46)|(uint64_t(64)<<32)|(uint64_t(1)<<16);
    return b|((a>>4)&0x3FFFu);
}
__device__ __forceinline__ void mma1(uint32_t d,uint64_t ad,uint64_t bd,uint32_t en){
    asm volatile("{.reg .pred p; setp.ne.u32 p,%4,0;\n\t"
        "tcgen05.mma.cta_group::1.kind::tf32 [%0],%1,%2,%3,{%5,%5,%5,%5},p;}"
        ::"r"(d),"l"(ad),"l"(bd),"r"(IDESC),"r"(en),"r"(0u):"memory");
}
__device__ __forceinline__ void mma_k64(uint32_t d,uint32_t a_s,uint32_t b_s,bool acc){
    uint64_t ad=sdesc(a_s),bd=sdesc(b_s);
#pragma unroll
    for(int s=0;s<8;++s)
        mma1(d,ad+(uint32_t)((s>>2)*1024+(s&3)*2),bd+(uint32_t)((s>>2)*512+(s&3)*2),(acc||s>0)?1u:0u);
}
// 3xTF32: D = Ah@Bh + Al@Bh + Ah@Bl
__device__ __forceinline__ void mma3(uint32_t d,uint32_t ah,uint32_t al,uint32_t bh,uint32_t bl,bool acc){
    mma_k64(d,ah,bh,acc);
    mma_k64(d,al,bh,true);
    mma_k64(d,ah,bl,true);
}
#define TCOMMIT(mb) asm volatile("tcgen05.commit.cta_group::1.mbarrier::arrive::one.shared::cluster.b64 [%0];"::"r"(mb):"memory")
#define FPA() asm volatile("fence.proxy.async.shared::cta;":::"memory")
#define TFA() asm volatile("tcgen05.fence::after_thread_sync;":::"memory")
#define TFB() asm volatile("tcgen05.fence::before_thread_sync;":::"memory")

__device__ __forceinline__ bool mb_poll(uint32_t mb,uint32_t par){
    for(int i=0;i<40000;++i){
        uint32_t d;
        asm volatile("{.reg .pred P; mbarrier.try_wait.parity.acquire.cta.shared::cta.b64 P,[%1],%2; selp.b32 %0,1,0,P;}"
            :"=r"(d):"r"(mb),"r"(par):"memory");
        if(d) return true;
    }
    return false;
}
__device__ __forceinline__ void ldtm16(uint32_t t,float* f){
    uint32_t r[16];
    asm volatile("tcgen05.ld.sync.aligned.32x32b.x16.b32 {%0,%1,%2,%3,%4,%5,%6,%7,%8,%9,%10,%11,%12,%13,%14,%15},[%16];"
        :"=r"(r[0]),"=r"(r[1]),"=r"(r[2]),"=r"(r[3]),"=r"(r[4]),"=r"(r[5]),"=r"(r[6]),"=r"(r[7]),
         "=r"(r[8]),"=r"(r[9]),"=r"(r[10]),"=r"(r[11]),"=r"(r[12]),"=r"(r[13]),"=r"(r[14]),"=r"(r[15])
        :"r"(t));
    asm volatile("tcgen05.wait::ld.sync.aligned;":::"memory");
#pragma unroll
    for(int i=0;i<16;++i) f[i]=__uint_as_float(r[i]);
}
// full-precision epilogue into one swizzled buffer
__device__ __forceinline__ void epi_full(uint32_t t,const float* bias,float* X,int m_r,int c0){
    float r[16]; ldtm16(t,r);
#pragma unroll
    for(int i=0;i<16;i+=4){
        float4 v=make_float4(r[i]+bias[i],r[i+1]+bias[i+1],r[i+2]+bias[i+2],r[i+3]+bias[i+3]);
        *reinterpret_cast<float4*>(X+axA(m_r,c0+i))=v;
    }
}
// split epilogue into hi/lo swizzled buffers (optionally relu)
__device__ __forceinline__ void epi_split(uint32_t t,const float* bias,float* H,float* L,int m_r,int c0,bool relu){
    float r[16]; ldtm16(t,r);
#pragma unroll
    for(int i=0;i<16;i+=4){
        float4 hv,lv;
        float v;
        v=r[i]+bias[i];     if(relu)v=fmaxf(v,0.f); split2(v,hv.x,lv.x);
        v=r[i+1]+bias[i+1]; if(relu)v=fmaxf(v,0.f); split2(v,hv.y,lv.y);
        v=r[i+2]+bias[i+2]; if(relu)v=fmaxf(v,0.f); split2(v,hv.z,lv.z);
        v=r[i+3]+bias[i+3]; if(relu)v=fmaxf(v,0.f); split2(v,hv.w,lv.w);
        *reinterpret_cast<float4*>(H+axA(m_r,c0+i))=hv;
        *reinterpret_cast<float4*>(L+axA(m_r,c0+i))=lv;
    }
}
__device__ __forceinline__ void cp_f4m(float* d,const float* s,int n4,int tid){
    for(int i=tid;i<n4;i+=NTM) reinterpret_cast<float4*>(d)[i]=reinterpret_cast<const float4*>(s)[i];
}
// copy one hi/lo B tile pair into an 8192-float region
__device__ __forceinline__ void cp_pair(float* dst,int tile,int tid){
    const float4* h=reinterpret_cast<const float4*>(g_B+((size_t)tile<<12));
    const float4* lo=reinterpret_cast<const float4*>(g_B+((size_t)(tile+88)<<12));
    for(int i=tid;i<1024;i+=NTM){
        reinterpret_cast<float4*>(dst)[i]=h[i];
        reinterpret_cast<float4*>(dst)[i+1024]=lo[i];
    }
}
__device__ __forceinline__ void cp_slicem(float* d,const float* s,int tid){
    for(int i=tid;i<1024;i+=NTM){int r=i>>4,c=i&15;
        reinterpret_cast<float4*>(d)[i]=reinterpret_cast<const float4*>(s+r*256)[c];}
}
// residual + LN, X kept as hi/lo split; Y swizzled full fp32
__device__ __forceinline__ void ln_split(const float* Y,float* XH,float* XL,
        const float* g,const float* be,int w,int l){
    float g0=g[l],g1v=g[l+32],e0=be[l],e1v=be[l+32];
#pragma unroll
    for(int i=0;i<8;++i){
        int r=w*8+i,i0=axA(r,l),i1=axA(r,l+32);
        float v0=Y[i0]+XH[i0]+XL[i0], v1=Y[i1]+XH[i1]+XL[i1];
        float s=v0+v1;
#pragma unroll
        for(int o=16;o>=1;o>>=1)s+=__shfl_xor_sync(0xffffffffu,s,o);
        float m=s*(1.f/64.f),d0=v0-m,d1=v1-m,q=d0*d0+d1*d1;
#pragma unroll
        for(int o=16;o>=1;o>>=1)q+=__shfl_xor_sync(0xffffffffu,q,o);
        float inv=rsqrtf(q*(1.f/64.f)+LN_EPS);
        float a=d0*inv*g0+e0, b=d1*inv*g1v+e1v;
        split2(a,XH[i0],XL[i0]);
        split2(b,XH[i1],XL[i1]);
    }
}
#define WAITX do{ if(ok) ok=mb_poll(mbv[wc&1],(uint32_t)((wc>>1)&1)); wc++; }while(0)
#endif

extern "C" __global__ void __launch_bounds__(512,1)
#if HAS_TC
__cluster_dims__(1,1,1)
#endif
radiance_mma(const float* __restrict__ query,const float* __restrict__ latent,
        const float* __restrict__ b1,const float* __restrict__ bq,const float* __restrict__ bk,
        const float* __restrict__ bv,const float* __restrict__ bo,const float* __restrict__ fb1,
        const float* __restrict__ fb2,const float* __restrict__ g1,const float* __restrict__ be1,
        const float* __restrict__ g2,const float* __restrict__ be2,const float* __restrict__ cWq,
        const float* __restrict__ cbq,const float* __restrict__ cbk,const float* __restrict__ cbv,
        const float* __restrict__ cWo,const float* __restrict__ cbo,const float* __restrict__ Wc,
        const float* __restrict__ bc,const float* __restrict__ Ws,const float* __restrict__ bs,
        float* __restrict__ out){
#if HAS_TC
    extern __shared__ float smem[];
    float* XH=smem+O_XH; float* XL=smem+O_XL;
    float* R1=smem+O_R1; float* R2=smem+O_R2; float* R3=smem+O_R3; float* R4=smem+O_R4;
    float* SP=smem+O_SP; float* QC=smem+O_QC; float* SQI=smem+O_SQI;
    const int tid=threadIdx.x,wid=tid>>5,l=tid&31,w=wid;
    const int b0=blockIdx.x*16;
    const int m_r=(wid&3)*32+l, c0=(wid>>2)*16;
    uint32_t sb=s2u(smem), ctl=sb+O_CTL*4;
    uint32_t mbv[2]={ctl+8,ctl+16};
    int cc=0, wc=0; bool ok=true;

    if(tid==0){
        asm volatile("mbarrier.init.shared.b64 [%0],1;"::"r"(mbv[0]):"memory");
        asm volatile("mbarrier.init.shared.b64 [%0],1;"::"r"(mbv[1]):"memory");
    }
    if(wid==0){
        asm volatile("tcgen05.alloc.cta_group::1.sync.aligned.shared::cta.b32 [%0],%1;"::"r"(ctl),"r"(256u):"memory");
        asm volatile("tcgen05.relinquish_alloc_permit.cta_group::1.sync.aligned;");
    }
    FPA(); __syncthreads();
    uint32_t tb; asm("ld.shared.b32 %0,[%1];":"=r"(tb):"r"(ctl));
    const uint32_t DQ=tb,DK=tb+64,DV=tb+128,DO=tb+192;
    const uint32_t aXH=sb+O_XH*4,aXL=sb+O_XL*4;
    const uint32_t aR1=sb+O_R1*4,aR2=sb+O_R2*4,aR3=sb+O_R3*4,aR4=sb+O_R4*4;
    float* attn_out=out+OFF_ATTN;

    // ======== stage0: X = relu(latent@W1+b1), K=512 in 8 chunks ========
    // A hi/lo ping-pong: (R1,R2) / (R3,R4); B pair ping-pong: XH / XL regions
    for(int ch=0;ch<8;++ch){
        if(ch>=2) WAITX;
        float* Ah=(ch&1)?R3:R1; float* Al=(ch&1)?R4:R2;
        float* Bp=(ch&1)?XL:XH;
        uint32_t aAh=(ch&1)?aR3:aR1, aAl=(ch&1)?aR4:aR2;
        uint32_t aBp=(ch&1)?aXL:aXH;
        for(int i=tid;i<2048;i+=NTM){
            int m=i>>4,k4=(i&15)<<2;
            float4 v=*reinterpret_cast<const float4*>(latent+(size_t)(b0*8+m)*512+ch*64+k4);
            float4 hv,lv;
            split2(v.x,hv.x,lv.x); split2(v.y,hv.y,lv.y);
            split2(v.z,hv.z,lv.z); split2(v.w,hv.w,lv.w);
            *reinterpret_cast<float4*>(Ah+axA(m,k4))=hv;
            *reinterpret_cast<float4*>(Al+axA(m,k4))=lv;
        }
        cp_pair(Bp,ch,tid);
        FPA(); __syncthreads();
        if(wid==0){ TFA();
            if(elect1()){
                mma3(DQ,aAh,aAl,aBp,aBp+16384,ch>0);
                TCOMMIT(mbv[cc&1]);
            }
        }
        cc++;
    }
    WAITX; WAITX;
    TFA();
    epi_split(DQ+c0,b1+c0,XH,XL,m_r,c0,true);
    TFB(); FPA(); __syncthreads();

    // ======== 4 transformer layers ========
    for(int li=0;li<4;++li){
        for(int h=0;h<4;++h){
            if(h>0) WAITX;                 // O-mma(h-1) retired -> R1..R4 free
            int base=8+(li*4+h)*3;
            cp_pair(R1,base,tid);          // Bq hi/lo
            cp_pair(R2,base+1,tid);        // Bk
            cp_pair(R3,base+2,tid);        // Bv
            cp_pair(R4,56+li*4+h,tid);     // Wo
            FPA(); __syncthreads();
            if(wid==0){ TFA();
                if(elect1()){
                    mma3(DQ,aXH,aXL,aR1,aR1+16384,false);
                    mma3(DK,aXH,aXL,aR2,aR2+16384,false);
                    mma3(DV,aXH,aXL,aR3,aR3+16384,false);
                    TCOMMIT(mbv[cc&1]);
                }
            }
            cc++;
            WAITX;
            TFA();
            epi_full(DQ+c0,bq+li*256+h*64+c0,R1,m_r,c0);  // Q (overwrites Bq, retired)
            epi_full(DK+c0,bk+li*256+h*64+c0,R2,m_r,c0);  // K
            epi_full(DV+c0,bv+li*256+h*64+c0,R3,m_r,c0);  // V
            TFB();
            __syncthreads();
            {   // per-warp attention (warp == batch); all reads/writes warp-local rows
                const int qi=l>>3,kj=l&7;
                float s0=0.f,s1=0.f;
#pragma unroll
                for(int d4=0;d4<64;d4+=4){
                    float4 kv=*reinterpret_cast<const float4*>(R2+axA(w*8+kj,d4));
                    float4 q0=*reinterpret_cast<const float4*>(R1+axA(w*8+qi,d4));
                    float4 q1=*reinterpret_cast<const float4*>(R1+axA(w*8+qi+4,d4));
                    s0+=q0.x*kv.x+q0.y*kv.y+q0.z*kv.z+q0.w*kv.w;
                    s1+=q1.x*kv.x+q1.y*kv.y+q1.z*kv.z+q1.w*kv.w;
                }
                s0*=SC_ATT;s1*=SC_ATT;
                float m0=s0,m1=s1;
#pragma unroll
                for(int o=1;o<8;o<<=1){
                    m0=fmaxf(m0,__shfl_xor_sync(0xffffffffu,m0,o));
                    m1=fmaxf(m1,__shfl_xor_sync(0xffffffffu,m1,o));
                }
                float e0=__expf(s0-m0),e1=__expf(s1-m1),t0=e0,t1=e1;
#pragma unroll
                for(int o=1;o<8;o<<=1){
                    t0+=__shfl_xor_sync(0xffffffffu,t0,o);
                    t1+=__shfl_xor_sync(0xffffffffu,t1,o);
                }
                float p0=e0/t0,p1=e1/t1;
                SP[w*64+l]=p0; SP[w*64+32+l]=p1;
                size_t ab=(size_t)(b0+w)*1024+li*256+h*64;
                attn_out[ab+l]=p0; attn_out[ab+32+l]=p1;
                __syncwarp();
                float a0[8],a1[8];
#pragma unroll
                for(int q2=0;q2<8;++q2){a0[q2]=0.f;a1[q2]=0.f;}
#pragma unroll
                for(int kk=0;kk<8;++kk){
                    float v0=R3[axA(w*8+kk,l)],v1=R3[axA(w*8+kk,l+32)];
#pragma unroll
                    for(int q2=0;q2<8;++q2){
                        float p=SP[w*64+q2*8+kk];
                        a0[q2]+=p*v0; a1[q2]+=p*v1;
                    }
                }
#pragma unroll
                for(int q2=0;q2<8;++q2){   // ctx hi->R1, lo->R2 (own rows: Q,K dead)
                    split2(a0[q2],R1[axA(w*8+q2,l)],R2[axA(w*8+q2,l)]);
                    split2(a1[q2],R1[axA(w*8+q2,l+32)],R2[axA(w*8+q2,l+32)]);
                }
            }
            FPA(); __syncthreads();
            if(wid==0){ TFA();
                if(elect1()){ mma3(DO,aR1,aR2,aR4,aR4+16384,h>0); TCOMMIT(mbv[cc&1]); }
            }
            cc++;
        } // heads
        WAITX;
        TFA();
        epi_full(DO+c0,bo+li*64+c0,R1,m_r,c0);   // Y (ctx retired)
        TFB(); __syncthreads();
        ln_split(R1,XH,XL,g1+li*64,be1+li*64,w,l);
        cp_pair(R2,72+li*2,tid);                 // fW1
        FPA(); __syncthreads();
        if(wid==0){ TFA();
            if(elect1()){ mma3(DQ,aXH,aXL,aR2,aR2+16384,false); TCOMMIT(mbv[cc&1]); }
        }
        cc++;
        WAITX;
        TFA();
        epi_split(DQ+c0,fb1+li*64+c0,R3,R4,m_r,c0,true);   // h1 hi/lo
        TFB();
        cp_pair(R2,73+li*2,tid);                 // fW2 (retired)
        FPA(); __syncthreads();
        if(wid==0){ TFA();
            if(elect1()){ mma3(DK,aR3,aR4,aR2,aR2+16384,false); TCOMMIT(mbv[cc&1]); }
        }
        cc++;
        WAITX;
        TFA();
        epi_full(DK+c0,fb2+li*64+c0,R1,m_r,c0);  // Y2
        TFB(); __syncthreads();
        ln_split(R1,XH,XL,g2+li*64,be2+li*64,w,l);
        FPA(); __syncthreads();
    } // layers

    // ======== cross attention ========
    for(int i=tid;i<1024;i+=NTM) SQI[i]=query[(size_t)(b0+(i>>6))*64+(i&63)];
    float ca0=0.f,ca1=0.f;
    for(int h=0;h<4;++h){
        cp_pair(R1,80+h,tid);                // cWk hi/lo
        cp_pair(R2,84+h,tid);                // cWv hi/lo
        cp_slicem(R3,cWq+h*64,tid);          // cWq slice linear [64][64]
        cp_f4m(R3+4096,cWo+h*4096,1024,tid); // cWo rows h*64.. linear
        FPA(); __syncthreads();
        if(wid==0){ TFA();
            if(elect1()){
                mma3(DQ,aXH,aXL,aR1,aR1+16384,false);   // Kc
                mma3(DK,aXH,aXL,aR2,aR2+16384,false);   // Vc
                TCOMMIT(mbv[cc&1]);
            }
        }
        cc++;
        for(int c=l;c<64;c+=32){             // Qc row per warp (fp32)
            float a=0.f;
#pragma unroll 8
            for(int k2=0;k2<64;++k2) a+=SQI[w*64+k2]*R3[k2*64+c];
            QC[w*64+c]=a+cbq[h*64+c];
        }
        WAITX;
        TFA();
        epi_full(DQ+c0,cbk+h*64+c0,R1,m_r,c0);   // Kc swz
        epi_full(DK+c0,cbv+h*64+c0,R2,m_r,c0);   // Vc swz
        TFB();
        __syncthreads();
        {   // 1x8 attention per warp
            const int j=l>>2,part=l&3;
            float sc=0.f;
#pragma unroll
            for(int d=part*16;d<part*16+16;++d) sc+=QC[w*64+d]*R1[axA(w*8+j,d)];
            sc+=__shfl_xor_sync(0xffffffffu,sc,1);
            sc+=__shfl_xor_sync(0xffffffffu,sc,2);
            sc*=SC_ATT;
            if(part==0) SP[w*64+j]=sc;
            __syncwarp();
            float mx=-1e30f;
#pragma unroll
            for(int jj=0;jj<8;++jj) mx=fmaxf(mx,SP[w*64+jj]);
            float pe[8],ss=0.f;
#pragma unroll
            for(int jj=0;jj<8;++jj){pe[jj]=__expf(SP[w*64+jj]-mx);ss+=pe[jj];}
            float inv=1.f/ss;
            for(int c=l;c<64;c+=32){
                float a=0.f;
#pragma unroll
                for(int jj=0;jj<8;++jj) a+=pe[jj]*R2[axA(w*8+jj,c)];
                QC[w*64+c]=a*inv;           // ctx row replaces Qc (own row, consumed)
            }
            __syncwarp();
#pragma unroll 8
            for(int k2=0;k2<64;++k2){
                float cv=QC[w*64+k2];
                ca0+=cv*R3[4096+k2*64+l];
                ca1+=cv*R3[4096+k2*64+32+l];
            }
        }
        __syncthreads();
    }
    // ======== heads: color, sigma, out ========
    {
        float a0=fmaxf(ca0+cbo[l],0.f),a1=fmaxf(ca1+cbo[l+32],0.f);
#pragma unroll
        for(int cq=0;cq<3;++cq){
            float p=a0*Wc[l*3+cq]+a1*Wc[(l+32)*3+cq];
#pragma unroll
            for(int o=16;o>=1;o>>=1)p+=__shfl_xor_sync(0xffffffffu,p,o);
            if(l==0) out[(size_t)(b0+w)*3+cq]=p+bc[cq];
        }
        float m0=-1e30f,m1=-1e30f;
#pragma unroll
        for(int s2=0;s2<8;++s2){
            int i0=axA(w*8+s2,l), i1=axA(w*8+s2,l+32);
            m0=fmaxf(m0,XH[i0]+XL[i0]);
            m1=fmaxf(m1,XH[i1]+XL[i1]);
        }
        float p=m0*Ws[l]+m1*Ws[l+32];
#pragma unroll
        for(int o=16;o>=1;o>>=1)p+=__shfl_xor_sync(0xffffffffu,p,o);
        if(l==0) out[OFF_SIGMA+b0+w]=p+bs[0];
    }
    for(int i=tid;i<8192;i+=NTM){
        int ix=axA(i>>6,i&63);
        out[OFF_OUT+(size_t)b0*512+i]=XH[ix]+XL[ix];
    }

    __syncthreads();
    if(wid==0)
        asm volatile("tcgen05.dealloc.cta_group::1.sync.aligned.b32 %0,%1;"::"r"(tb),"r"(256u));

    int allok=__syncthreads_and(ok?1:0);
    if(tid==0&&allok) atomicAdd(&g_ok,1);
#else
    (void)query;(void)latent;(void)b1;(void)bq;(void)bk;(void)bv;(void)bo;(void)fb1;(void)fb2;
    (void)g1;(void)be1;(void)g2;(void)be2;(void)cWq;(void)cbq;(void)cbk;(void)cbv;(void)cWo;
    (void)cbo;(void)Wc;(void)bc;(void)Ws;(void)bs;(void)out;
#endif
}

// =====================================================================
//  FFMA fallback — early-exits when MMA path fully succeeded
// =====================================================================
#define NTF 256
#define F_SX   0
#define F_SCTX 4096
#define F_ST   (4096+16384)
#define F_SW   (F_ST+12288)
#define F_SP   (F_SW+16384)
#define F_SQI  (F_SP+512)
#define F_SCA  (F_SQI+512)
#define F_SMEMF 50688

typedef unsigned long long ull;
__device__ __forceinline__ ull pk2(float lo,float hi){
    ull r; asm("mov.b64 %0,{%1,%2};":"=l"(r):"r"(__float_as_uint(lo)),"r"(__float_as_uint(hi))); return r;
}
__device__ __forceinline__ void fma2(ull &a,ull b,ull c){
    asm("fma.rn.f32x2 %0,%1,%2,%0;":"+l"(a):"l"(b),"l"(c));
}
__device__ __forceinline__ float2 upk(ull v){
    unsigned lo,hi; asm("mov.b64 {%0,%1},%2;":"=r"(lo),"=r"(hi):"l"(v));
    return make_float2(__uint_as_float(lo),__uint_as_float(hi));
}
__device__ __forceinline__ void cp_f4f(float* d,const float* s,int n4,int tid){
    for(int i=tid;i<n4;i+=NTF) reinterpret_cast<float4*>(d)[i]=reinterpret_cast<const float4*>(s)[i];
}
__device__ __forceinline__ void cp_slicef(float* d,const float* s,int tid){
    for(int i=tid;i<1024;i+=NTF){int r=i>>4,c=i&15;
        reinterpret_cast<float4*>(d)[i]=reinterpret_cast<const float4*>(s+r*256)[c];}
}
template<int K,int LDX>
__device__ __forceinline__ void gemm_accF(const float* X,const float* W,ull a01[4],ull a23[4],int c0,int rb){
#pragma unroll 8
    for(int k=0;k<K;++k){
        float4 wv=*reinterpret_cast<const float4*>(W+k*64+c0);
        ull w01=pk2(wv.x,wv.y),w23=pk2(wv.z,wv.w);
#pragma unroll
        for(int r=0;r<4;++r){
            float xv=X[(rb+r)*LDX+k];
            ull xx=pk2(xv,xv);
            fma2(a01[r],w01,xx); fma2(a23[r],w23,xx);
        }
    }
}
template<int K,int LDX,bool RELU>
__device__ __forceinline__ void gemm_blockF(const float* X,const float* W,const float* bias,float* Y,int tid){
    const int c0=(tid&15)*4, rb=(tid>>4)*4;
    ull a01[4]={0,0,0,0},a23[4]={0,0,0,0};
    gemm_accF<K,LDX>(X,W,a01,a23,c0,rb);
    float b0v=bias[c0],b1v=bias[c0+1],b2v=bias[c0+2],b3v=bias[c0+3];
#pragma unroll
    for(int r=0;r<4;++r){
        float2 v01=upk(a01[r]),v23=upk(a23[r]);
        float o0=v01.x+b0v,o1=v01.y+b1v,o2=v23.x+b2v,o3=v23.y+b3v;
        if(RELU){o0=fmaxf(o0,0.f);o1=fmaxf(o1,0.f);o2=fmaxf(o2,0.f);o3=fmaxf(o3,0.f);}
        *reinterpret_cast<float4*>(Y+(rb+r)*64+c0)=make_float4(o0,o1,o2,o3);
    }
}
__device__ __forceinline__ void ln_blockF(const float* Yd,float* Xs,const float* g,const float* be,int w,int l){
    float g0=g[l],g1v=g[l+32],e0=be[l],e1v=be[l+32];
#pragma unroll
    for(int i=0;i<8;++i){
        int r=w*8+i;
        float v0=Yd[r*64+l]+Xs[r*64+l];
        float v1=Yd[r*64+32+l]+Xs[r*64+32+l];
        float s=v0+v1;
#pragma unroll
        for(int o=16;o>=1;o>>=1)s+=__shfl_xor_sync(0xffffffffu,s,o);
        float m=s*(1.f/64.f),d0=v0-m,d1=v1-m,q=d0*d0+d1*d1;
#pragma unroll
        for(int o=16;o>=1;o>>=1)q+=__shfl_xor_sync(0xffffffffu,q,o);
        float inv=rsqrtf(q*(1.f/64.f)+LN_EPS);
        Xs[r*64+l]=d0*inv*g0+e0; Xs[r*64+32+l]=d1*inv*g1v+e1v;
    }
}

extern "C" __global__ void __launch_bounds__(256,1)
radiance_ffma(const float* __restrict__ query,const float* __restrict__ latent,
        const float* __restrict__ W1,const float* __restrict__ b1,
        const float* __restrict__ Wq,const float* __restrict__ bq,
        const float* __restrict__ Wk,const float* __restrict__ bk,
        const float* __restrict__ Wv,const float* __restrict__ bv,
        const float* __restrict__ Wo,const float* __restrict__ bo,
        const float* __restrict__ fW1,const float* __restrict__ fb1,
        const float* __restrict__ fW2,const float* __restrict__ fb2,
        const float* __restrict__ g1,const float* __restrict__ be1,
        const float* __restrict__ g2,const float* __restrict__ be2,
        const float* __restrict__ cWq,const float* __restrict__ cbq,
        const float* __restrict__ cWk,const float* __restrict__ cbk,
        const float* __restrict__ cWv,const float* __restrict__ cbv,
        const float* __restrict__ cWo,const float* __restrict__ cbo,
        const float* __restrict__ Wc,const float* __restrict__ bc,
        const float* __restrict__ Ws,const float* __restrict__ bs,
        float* __restrict__ out){
    if(*(volatile int*)&g_ok==MMA_GRID) return;
    extern __shared__ float smem[];
    float* SX=smem+F_SX; float* SCTX=smem+F_SCTX; float* ST=smem+F_ST;
    float* SW=smem+F_SW; float* SP=smem+F_SP; float* SQI=smem+F_SQI; float* SCA=smem+F_SCA;
    const int tid=threadIdx.x, w=tid>>5, l=tid&31, b0=blockIdx.x*8;
    float* attn_out=out+OFF_ATTN;

    {
        const int c0=(tid&15)*4, rb=(tid>>4)*4;
        ull a01[4]={0,0,0,0},a23[4]={0,0,0,0};
        for(int ch=0;ch<4;++ch){
            __syncthreads();
            cp_f4f(SW,W1+ch*8192,2048,tid);
            for(int i=tid;i<2048;i+=NTF){
                int r=i>>5,j=i&31;
                reinterpret_cast<float4*>(ST)[i]=
                    *reinterpret_cast<const float4*>(latent+(size_t)(b0*8+r)*512+ch*128+j*4);
            }
            __syncthreads();
            gemm_accF<128,128>(ST,SW,a01,a23,c0,rb);
        }
        float b0v=b1[c0],b1v=b1[c0+1],b2v=b1[c0+2],b3v=b1[c0+3];
#pragma unroll
        for(int r=0;r<4;++r){
            float2 v01=upk(a01[r]),v23=upk(a23[r]);
            *reinterpret_cast<float4*>(SX+(rb+r)*64+c0)=
                make_float4(fmaxf(v01.x+b0v,0.f),fmaxf(v01.y+b1v,0.f),
                            fmaxf(v23.x+b2v,0.f),fmaxf(v23.y+b3v,0.f));
        }
    }

    for(int li=0;li<4;++li){
        const float* Wq_i=Wq+li*16384; const float* Wk_i=Wk+li*16384;
        const float* Wv_i=Wv+li*16384;
        for(int h=0;h<4;++h){
            __syncthreads();
            cp_slicef(SW,Wq_i+h*64,tid);
            cp_slicef(SW+4096,Wk_i+h*64,tid);
            cp_slicef(SW+8192,Wv_i+h*64,tid);
            __syncthreads();
            gemm_blockF<64,64,false>(SX,SW,bq+li*256+h*64,ST,tid);
            gemm_blockF<64,64,false>(SX,SW+4096,bk+li*256+h*64,ST+4096,tid);
            gemm_blockF<64,64,false>(SX,SW+8192,bv+li*256+h*64,ST+8192,tid);
            __syncthreads();
            {
                const float* qB=ST+w*512; const float* kB=ST+4096+w*512; const float* vB=ST+8192+w*512;
                int qi=l>>3,kj=l&7;
                float s0=0.f,s1=0.f;
#pragma unroll 8
                for(int d=0;d<64;++d){
                    float kv=kB[kj*64+d];
                    s0+=qB[qi*64+d]*kv; s1+=qB[(qi+4)*64+d]*kv;
                }
                s0*=SC_ATT;s1*=SC_ATT;
                float m0=s0,m1=s1;
#pragma unroll
                for(int o=1;o<8;o<<=1){
                    m0=fmaxf(m0,__shfl_xor_sync(0xffffffffu,m0,o));
                    m1=fmaxf(m1,__shfl_xor_sync(0xffffffffu,m1,o));
                }
                float e0=expf(s0-m0),e1=expf(s1-m1),t0=e0,t1=e1;
#pragma unroll
                for(int o=1;o<8;o<<=1){
                    t0+=__shfl_xor_sync(0xffffffffu,t0,o);
                    t1+=__shfl_xor_sync(0xffffffffu,t1,o);
                }
                float p0=e0/t0,p1=e1/t1;
                SP[w*64+l]=p0; SP[w*64+32+l]=p1;
                size_t ab=(size_t)(b0+w)*1024+li*256+h*64;
                attn_out[ab+l]=p0; attn_out[ab+32+l]=p1;
                __syncwarp();
#pragma unroll
                for(int qq=0;qq<8;++qq){
                    float a0=0.f,a1=0.f;
#pragma unroll
                    for(int kk2=0;kk2<8;++kk2){
                        float p=SP[w*64+qq*8+kk2];
                        a0+=p*vB[kk2*64+l]; a1+=p*vB[kk2*64+32+l];
                    }
                    SCTX[(w*8+qq)*256+h*64+l]=a0;
                    SCTX[(w*8+qq)*256+h*64+32+l]=a1;
                }
            }
        }
        __syncthreads();
        cp_f4f(SW,Wo+li*16384,4096,tid);
        __syncthreads();
        gemm_blockF<256,256,false>(SCTX,SW,bo+li*64,ST,tid);
        __syncthreads();
        ln_blockF(ST,SX,g1+li*64,be1+li*64,w,l);
        __syncthreads();
        cp_f4f(SW,fW1+li*4096,1024,tid);
        cp_f4f(SW+4096,fW2+li*4096,1024,tid);
        __syncthreads();
        gemm_blockF<64,64,true>(SX,SW,fb1+li*64,ST+4096,tid);
        __syncthreads();
        gemm_blockF<64,64,false>(ST+4096,SW+4096,fb2+li*64,ST,tid);
        __syncthreads();
        ln_blockF(ST,SX,g2+li*64,be2+li*64,w,l);
    }

    for(int i=tid;i<512;i+=NTF)
        SQI[i]=query[(size_t)(b0+(i>>6))*64+(i&63)];

    for(int h=0;h<4;++h){
        __syncthreads();
        cp_slicef(SW,cWq+h*64,tid);
        cp_slicef(SW+4096,cWk+h*64,tid);
        cp_slicef(SW+8192,cWv+h*64,tid);
        __syncthreads();
        gemm_blockF<64,64,false>(SX,SW+4096,cbk+h*64,ST,tid);
        gemm_blockF<64,64,false>(SX,SW+8192,cbv+h*64,ST+4096,tid);
        for(int c=l;c<64;c+=32){
            float a=0.f;
#pragma unroll 8
            for(int k2=0;k2<64;++k2) a+=SQI[w*64+k2]*SW[k2*64+c];
            ST[8192+w*64+c]=a+cbq[h*64+c];
        }
        __syncthreads();
        {
            int j=l>>2,part=l&3;
            const float* qrow=ST+8192+w*64; const float* kB=ST+w*512;
            float sc=0.f;
#pragma unroll
            for(int d=part*16;d<part*16+16;++d) sc+=qrow[d]*kB[j*64+d];
            sc+=__shfl_xor_sync(0xffffffffu,sc,1);
            sc+=__shfl_xor_sync(0xffffffffu,sc,2);
            sc*=SC_ATT;
            if(part==0) SP[w*8+j]=sc;
            __syncwarp();
            float mx=-1e30f;
#pragma unroll
            for(int jj=0;jj<8;++jj) mx=fmaxf(mx,SP[w*8+jj]);
            float pe[8],ssum=0.f;
#pragma unroll
            for(int jj=0;jj<8;++jj){pe[jj]=expf(SP[w*8+jj]-mx);ssum+=pe[jj];}
            float inv=1.f/ssum;
            const float* vB=ST+4096+w*512;
            for(int c=l;c<64;c+=32){
                float a=0.f;
#pragma unroll
                for(int jj=0;jj<8;++jj) a+=pe[jj]*vB[jj*64+c];
                SCTX[(w*8)*256+h*64+c]=a*inv;
            }
        }
    }
    __syncthreads();
    cp_f4f(SW,cWo,4096,tid);
    __syncthreads();
    {
        const float* ctx=SCTX+w*2048;
        float a0=0.f,a1=0.f;
#pragma unroll 8
        for(int k2=0;k2<256;++k2){
            float cv=ctx[k2];
            a0+=cv*SW[k2*64+l]; a1+=cv*SW[k2*64+32+l];
        }
        a0=fmaxf(a0+cbo[l],0.f); a1=fmaxf(a1+cbo[l+32],0.f);
        SCA[w*64+l]=a0; SCA[w*64+32+l]=a1;
        __syncwarp();
#pragma unroll
        for(int cq=0;cq<3;++cq){
            float p=SCA[w*64+l]*Wc[l*3+cq]+SCA[w*64+32+l]*Wc[(l+32)*3+cq];
#pragma unroll
            for(int o=16;o>=1;o>>=1)p+=__shfl_xor_sync(0xffffffffu,p,o);
            if(l==0) out[(size_t)(b0+w)*3+cq]=p+bc[cq];
        }
        float m0=-1e30f,m1=-1e30f;
#pragma unroll
        for(int s2=0;s2<8;++s2){
            m0=fmaxf(m0,SX[(w*8+s2)*64+l]);
            m1=fmaxf(m1,SX[(w*8+s2)*64+32+l]);
        }
        float p=m0*Ws[l]+m1*Ws[l+32];
#pragma unroll
        for(int o=16;o>=1;o>>=1)p+=__shfl_xor_sync(0xffffffffu,p,o);
        if(l==0) out[OFF_SIGMA+b0+w]=p+bs[0];
    }
    for(int i=tid;i<4096;i+=NTF)
        out[OFF_OUT+(size_t)b0*512+i]=SX[i];
}

extern "C" void kernel_launch(void* const* d_in,const int* in_sizes,int n_in,
                              void* d_out,int out_size){
    (void)in_sizes;(void)n_in;(void)out_size;
    const float* query=(const float*)d_in[0];
    const float* latent=(const float*)d_in[1];
    const float* W1=(const float*)d_in[2];  const float* b1=(const float*)d_in[3];
    const float* Wq=(const float*)d_in[4];  const float* bq=(const float*)d_in[5];
    const float* Wk=(const float*)d_in[6];  const float* bk=(const float*)d_in[7];
    const float* Wv=(const float*)d_in[8];  const float* bv=(const float*)d_in[9];
    const float* Wo=(const float*)d_in[10]; const float* bo=(const float*)d_in[11];
    const float* fW1=(const float*)d_in[12];const float* fb1=(const float*)d_in[13];
    const float* fW2=(const float*)d_in[14];const float* fb2=(const float*)d_in[15];
    const float* g1=(const float*)d_in[16]; const float* be1=(const float*)d_in[17];
    const float* g2=(const float*)d_in[18]; const float* be2=(const float*)d_in[19];
    const float* cWq=(const float*)d_in[20];const float* cbq=(const float*)d_in[21];
    const float* cWk=(const float*)d_in[22];const float* cbk=(const float*)d_in[23];
    const float* cWv=(const float*)d_in[24];const float* cbv=(const float*)d_in[25];
    const float* cWo=(const float*)d_in[26];const float* cbo=(const float*)d_in[27];
    const float* Wc=(const float*)d_in[28]; const float* bc=(const float*)d_in[29];
    const float* Ws=(const float*)d_in[30]; const float* bs=(const float*)d_in[31];
    float* out=(float*)d_out;

    reset_kernel<<<1,1>>>();
    prep_kernel<<<(88*4096+255)/256,256>>>(W1,Wq,Wk,Wv,Wo,fW1,fW2,cWk,cWv);

    const int smem_mma=52240*sizeof(float);
    cudaFuncSetAttribute(radiance_mma,cudaFuncAttributeMaxDynamicSharedMemorySize,smem_mma);
    radiance_mma<<<MMA_GRID,512,smem_mma>>>(query,latent,b1,bq,bk,bv,bo,fb1,fb2,
        g1,be1,g2,be2,cWq,cbq,cbk,cbv,cWo,cbo,Wc,bc,Ws,bs,out);

    const int smem_ffma=F_SMEMF*sizeof(float);
    cudaFuncSetAttribute(radiance_ffma,cudaFuncAttributeMaxDynamicSharedMemorySize,smem_ffma);
    radiance_ffma<<<BB/8,256,smem_ffma>>>(query,latent,W1,b1,Wq,bq,Wk,bk,Wv,bv,Wo,bo,
        fW1,fb1,fW2,fb2,g1,be1,g2,be2,cWq,cbq,cWk,cbk,cWv,cbv,cWo,cbo,Wc,bc,Ws,bs,out);
}

// round 10
// speedup vs baseline: 5.4962x; 1.4568x over previous
#include <cuda_runtime.h>
#include <cuda_bf16.h>
#include <stdint.h>
#include <math.h>

#if defined(__CUDA_ARCH_FEAT_SM103_ALL) || defined(__CUDA_ARCH_FEAT_SM100_ALL) || defined(__CUDA_ARCH_FEAT_SM101_ALL)
#define HAS_TC 1
#else
#define HAS_TC 0
#endif

#define BB 32768
#define LN_EPS 1e-5f
#define SC_ATT 0.125f
#define OFF_SIGMA (3*BB)
#define OFF_OUT (OFF_SIGMA+BB)
#define OFF_ATTN (OFF_OUT+(size_t)BB*512)
#define MMA_GRID 2048

__device__ __nv_bfloat16 g_Bh[88*8192];   // per tile: 4096 hi then 4096 lo
__device__ int g_ok;

extern "C" __global__ void reset_kernel(){ g_ok = 0; }

// fp32 swizzled A-tile index ([128][64] fp32, 32KB)
__device__ __forceinline__ int axAf(int m,int k){return ((k>>5)<<12)|((m>>3)<<8)|((m&7)<<5)|((k&31)^((m&7)<<2));}
// bf16 tile element index ([R rows][64 k] bf16; atom = 8 rows x 128B)
__device__ __forceinline__ int axHb(int r,int k){
    int byte=(r&7)*128+k*2; byte^=((byte>>3)&0x70);
    return ((r>>3)<<9)+(byte>>1);
}
__device__ __forceinline__ void sp2b(float v,__nv_bfloat16&h,__nv_bfloat16&l){
    h=__float2bfloat16(v); l=__float2bfloat16(v-(float)h);
}

extern "C" __global__ void prep_kernel(const float* W1,const float* Wq,const float* Wk,const float* Wv,
        const float* Wo,const float* fW1,const float* fW2,const float* cWk,const float* cWv){
    int idx=blockIdx.x*256+threadIdx.x;
    if(idx>=88*4096)return;
    int tile=idx>>12,j=idx&4095,n=j>>6,k=j&63;
    float v;
    if(tile<8) v=W1[(tile*64+k)*64+n];
    else if(tile<56){int t=tile-8,lh=t/3,wch=t%3,li=lh>>2,h=lh&3;
        const float* W=(wch==0)?Wq:((wch==1)?Wk:Wv);
        v=W[li*16384+k*256+h*64+n];}
    else if(tile<72){int t=tile-56,li=t>>2,h=t&3; v=Wo[li*16384+(h*64+k)*64+n];}
    else if(tile<80){int t=tile-72,li=t>>1; v=((t&1)?fW2:fW1)[li*4096+k*64+n];}
    else if(tile<84) v=cWk[k*256+(tile-80)*64+n];
    else v=cWv[k*256+(tile-84)*64+n];
    __nv_bfloat16 h,l; sp2b(v,h,l);
    int ax=axHb(n,k);
    g_Bh[(size_t)tile*8192+ax]=h;
    g_Bh[(size_t)tile*8192+4096+ax]=l;
}

#if HAS_TC
#define NTM 512
#define IDESC 0x8100490u     // bf16, M=128, N=64, fp32 accum
// smem float offsets: regions of 4096 floats (16KB)
#define O_XH 0
#define O_XL 4096
#define O_R0 8192
#define O_R1 12288
#define O_R2 16384
#define O_R3 20480
#define O_SP 24576
#define O_QC 25600
#define O_SQI 26624
#define O_CTL 27648
#define SMEMF 27664

__device__ __forceinline__ uint32_t s2u(const void* p){
    uint32_t a; asm("{.reg .u64 t; cvta.to.shared.u64 t,%1; cvt.u32.u64 %0,t;}":"=r"(a):"l"(p)); return a;
}
__device__ __forceinline__ uint32_t elect1(){
    uint32_t r; asm volatile("{.reg .pred p; elect.sync _|p,0xFFFFFFFF; selp.b32 %0,1,0,p;}":"=r"(r)); return r;
}
__device__ __forceinline__ uint64_t sdesc(uint32_t a){
    const uint64_t b=(uint64_t(2)<<61)|(uint64_t(1)<<46)|(uint64_t(64)<<32)|(uint64_t(1)<<16);
    return b|((a>>4)&0x3FFFu);
}
__device__ __forceinline__ void mma1(uint32_t d,uint64_t ad,uint64_t bd,uint32_t en){
    asm volatile("{.reg .pred p; setp.ne.u32 p,%4,0;\n\t"
        "tcgen05.mma.cta_group::1.kind::f16 [%0],%1,%2,%3,{%5,%5,%5,%5},p;}"
        ::"r"(d),"l"(ad),"l"(bd),"r"(IDESC),"r"(en),"r"(0u):"memory");
}
// D[128,64] (+)= A[128,64]bf16 @ B[64,64]bf16^T ; K=16 per step, 4 steps
__device__ __forceinline__ void mma_k64b(uint32_t d,uint32_t a_s,uint32_t b_s,bool acc){
    uint64_t ad=sdesc(a_s),bd=sdesc(b_s);
#pragma unroll
    for(int s=0;s<4;++s)
        mma1(d,ad+(uint32_t)(s*2),bd+(uint32_t)(s*2),(acc||s>0)?1u:0u);
}
// 3xBF16: D = Ah@Bh + Al@Bh + Ah@Bl
__device__ __forceinline__ void mma3b(uint32_t d,uint32_t ah,uint32_t al,uint32_t bh,uint32_t bl,bool acc){
    mma_k64b(d,ah,bh,acc);
    mma_k64b(d,al,bh,true);
    mma_k64b(d,ah,bl,true);
}
#define TCOMMIT(mb) asm volatile("tcgen05.commit.cta_group::1.mbarrier::arrive::one.shared::cluster.b64 [%0];"::"r"(mb):"memory")
#define FPA() asm volatile("fence.proxy.async.shared::cta;":::"memory")
#define TFA() asm volatile("tcgen05.fence::after_thread_sync;":::"memory")
#define TFB() asm volatile("tcgen05.fence::before_thread_sync;":::"memory")

__device__ __forceinline__ bool mb_poll(uint32_t mb,uint32_t par){
    for(int i=0;i<40000;++i){
        uint32_t d;
        asm volatile("{.reg .pred P; mbarrier.try_wait.parity.acquire.cta.shared::cta.b64 P,[%1],%2; selp.b32 %0,1,0,P;}"
            :"=r"(d):"r"(mb),"r"(par):"memory");
        if(d) return true;
    }
    return false;
}
__device__ __forceinline__ void ldtm16(uint32_t t,float* f){
    uint32_t r[16];
    asm volatile("tcgen05.ld.sync.aligned.32x32b.x16.b32 {%0,%1,%2,%3,%4,%5,%6,%7,%8,%9,%10,%11,%12,%13,%14,%15},[%16];"
        :"=r"(r[0]),"=r"(r[1]),"=r"(r[2]),"=r"(r[3]),"=r"(r[4]),"=r"(r[5]),"=r"(r[6]),"=r"(r[7]),
         "=r"(r[8]),"=r"(r[9]),"=r"(r[10]),"=r"(r[11]),"=r"(r[12]),"=r"(r[13]),"=r"(r[14]),"=r"(r[15])
        :"r"(t));
    asm volatile("tcgen05.wait::ld.sync.aligned;":::"memory");
#pragma unroll
    for(int i=0;i<16;++i) f[i]=__uint_as_float(r[i]);
}
// fp32 swizzled epilogue into 32KB buffer
__device__ __forceinline__ void epi_fullf(uint32_t t,const float* bias,float* X,int m_r,int c0){
    float r[16]; ldtm16(t,r);
#pragma unroll
    for(int i=0;i<16;i+=4){
        float4 v=make_float4(r[i]+bias[i],r[i+1]+bias[i+1],r[i+2]+bias[i+2],r[i+3]+bias[i+3]);
        *reinterpret_cast<float4*>(X+axAf(m_r,c0+i))=v;
    }
}
// split epilogue: bf16 hi/lo pairs into two 16KB tiles (packed bf16x2 stores)
__device__ __forceinline__ void epi_splitb(uint32_t t,const float* bias,
        __nv_bfloat16* Hb,__nv_bfloat16* Lb,int m_r,int c0,bool relu){
    float r[16]; ldtm16(t,r);
#pragma unroll
    for(int j=0;j<8;++j){
        float v0=r[2*j]+bias[2*j], v1=r[2*j+1]+bias[2*j+1];
        if(relu){v0=fmaxf(v0,0.f);v1=fmaxf(v1,0.f);}
        __nv_bfloat16 h0,l0,h1,l1;
        sp2b(v0,h0,l0); sp2b(v1,h1,l1);
        int k=c0+2*j;
        int byte=(m_r&7)*128+k*2; byte^=((byte>>3)&0x70);
        int base=((m_r>>3)<<10)+byte;
        __nv_bfloat162 hp; hp.x=h0; hp.y=h1;
        __nv_bfloat162 lp; lp.x=l0; lp.y=l1;
        *reinterpret_cast<__nv_bfloat162*>(reinterpret_cast<char*>(Hb)+base)=hp;
        *reinterpret_cast<__nv_bfloat162*>(reinterpret_cast<char*>(Lb)+base)=lp;
    }
}
__device__ __forceinline__ void cp_f4m(float* d,const float* s,int n4,int tid){
    for(int i=tid;i<n4;i+=NTM) reinterpret_cast<float4*>(d)[i]=reinterpret_cast<const float4*>(s)[i];
}
// copy one 16KB hi/lo bf16 tile pair
__device__ __forceinline__ void cp_pair(float* dst,int tile,int tid){
    const float4* s=reinterpret_cast<const float4*>(g_Bh+(size_t)tile*8192);
    for(int i=tid;i<1024;i+=NTM) reinterpret_cast<float4*>(dst)[i]=s[i];
}
__device__ __forceinline__ void cp_slicem(float* d,const float* s,int tid){
    for(int i=tid;i<1024;i+=NTM){int r=i>>4,c=i&15;
        reinterpret_cast<float4*>(d)[i]=reinterpret_cast<const float4*>(s+r*256)[c];}
}
// residual + LN; X persisted as bf16 hi/lo pair; Y fp32 swizzled
__device__ __forceinline__ void ln_b(const float* Y,__nv_bfloat16* XHb,__nv_bfloat16* XLb,
        const float* g,const float* be,int w,int l){
    float g0=g[l],g1v=g[l+32],e0=be[l],e1v=be[l+32];
#pragma unroll
    for(int i=0;i<8;++i){
        int r=w*8+i;
        int y0=axAf(r,l), y1=axAf(r,l+32);
        int b0i=axHb(r,l), b1i=axHb(r,l+32);
        float v0=Y[y0]+(float)XHb[b0i]+(float)XLb[b0i];
        float v1=Y[y1]+(float)XHb[b1i]+(float)XLb[b1i];
        float s=v0+v1;
#pragma unroll
        for(int o=16;o>=1;o>>=1)s+=__shfl_xor_sync(0xffffffffu,s,o);
        float m=s*(1.f/64.f),d0=v0-m,d1=v1-m,q=d0*d0+d1*d1;
#pragma unroll
        for(int o=16;o>=1;o>>=1)q+=__shfl_xor_sync(0xffffffffu,q,o);
        float inv=rsqrtf(q*(1.f/64.f)+LN_EPS);
        float a=d0*inv*g0+e0, b=d1*inv*g1v+e1v;
        sp2b(a,XHb[b0i],XLb[b0i]);
        sp2b(b,XHb[b1i],XLb[b1i]);
    }
}
#define WAITX do{ if(ok) ok=mb_poll(mbv[wc&1],(uint32_t)((wc>>1)&1)); wc++; }while(0)
#endif

extern "C" __global__ void __launch_bounds__(512,2)
#if HAS_TC
__cluster_dims__(1,1,1)
#endif
radiance_mma(const float* __restrict__ query,const float* __restrict__ latent,
        const float* __restrict__ b1,const float* __restrict__ bq,const float* __restrict__ bk,
        const float* __restrict__ bv,const float* __restrict__ bo,const float* __restrict__ fb1,
        const float* __restrict__ fb2,const float* __restrict__ g1,const float* __restrict__ be1,
        const float* __restrict__ g2,const float* __restrict__ be2,const float* __restrict__ cWq,
        const float* __restrict__ cbq,const float* __restrict__ cbk,const float* __restrict__ cbv,
        const float* __restrict__ cWo,const float* __restrict__ cbo,const float* __restrict__ Wc,
        const float* __restrict__ bc,const float* __restrict__ Ws,const float* __restrict__ bs,
        float* __restrict__ out){
#if HAS_TC
    extern __shared__ float smem[];
    float* R0f=smem+O_R0; float* R1f=smem+O_R1; float* R2f=smem+O_R2; float* R3f=smem+O_R3;
    __nv_bfloat16* XHb=reinterpret_cast<__nv_bfloat16*>(smem+O_XH);
    __nv_bfloat16* XLb=reinterpret_cast<__nv_bfloat16*>(smem+O_XL);
    float* SP=smem+O_SP; float* QC=smem+O_QC; float* SQI=smem+O_SQI;
    const int tid=threadIdx.x,wid=tid>>5,l=tid&31,w=wid;
    const int b0=blockIdx.x*16;
    const int m_r=(wid&3)*32+l, c0=(wid>>2)*16;
    uint32_t sb=s2u(smem), ctl=sb+O_CTL*4;
    uint32_t mbv[2]={ctl+8,ctl+16};
    int cc=0, wc=0; bool ok=true; (void)cc;

    if(tid==0){
        asm volatile("mbarrier.init.shared.b64 [%0],1;"::"r"(mbv[0]):"memory");
        asm volatile("mbarrier.init.shared.b64 [%0],1;"::"r"(mbv[1]):"memory");
    }
    if(wid==0){
        asm volatile("tcgen05.alloc.cta_group::1.sync.aligned.shared::cta.b32 [%0],%1;"::"r"(ctl),"r"(256u):"memory");
        asm volatile("tcgen05.relinquish_alloc_permit.cta_group::1.sync.aligned;");
    }
    FPA(); __syncthreads();
    uint32_t tb; asm("ld.shared.b32 %0,[%1];":"=r"(tb):"r"(ctl));
    const uint32_t DQ=tb,DK=tb+64,DV=tb+128,DO=tb+192;
    const uint32_t aXH=sb+O_XH*4,aXL=sb+O_XL*4;
    const uint32_t aR0=sb+O_R0*4,aR1=sb+O_R1*4,aR2=sb+O_R2*4,aR3=sb+O_R3*4;
    float* attn_out=out+OFF_ATTN;

    // ======== stage0: X = relu(latent@W1+b1), K=512 in 8 chunks ========
    for(int ch=0;ch<8;++ch){
        if(ch>=2) WAITX;
        __nv_bfloat16* Ah=reinterpret_cast<__nv_bfloat16*>((ch&1)?R2f:R0f);
        __nv_bfloat16* Al=reinterpret_cast<__nv_bfloat16*>((ch&1)?R3f:R1f);
        float* Bp=(ch&1)?(smem+O_XL):(smem+O_XH);
        uint32_t aAh=(ch&1)?aR2:aR0, aAl=(ch&1)?aR3:aR1;
        uint32_t aBp=(ch&1)?aXL:aXH;
        for(int i=tid;i<2048;i+=NTM){
            int m=i>>4,k4=(i&15)<<2;
            float4 v=*reinterpret_cast<const float4*>(latent+(size_t)(b0*8+m)*512+ch*64+k4);
            __nv_bfloat16 h0,l0,h1,l1,h2,l2,h3,l3;
            sp2b(v.x,h0,l0); sp2b(v.y,h1,l1); sp2b(v.z,h2,l2); sp2b(v.w,h3,l3);
            int byte=(m&7)*128+k4*2; byte^=((byte>>3)&0x70);
            int base=((m>>3)<<10)+byte;
            __nv_bfloat162 p01h; p01h.x=h0; p01h.y=h1;
            __nv_bfloat162 p23h; p23h.x=h2; p23h.y=h3;
            __nv_bfloat162 p01l; p01l.x=l0; p01l.y=l1;
            __nv_bfloat162 p23l; p23l.x=l2; p23l.y=l3;
            *reinterpret_cast<__nv_bfloat162*>(reinterpret_cast<char*>(Ah)+base)=p01h;
            *reinterpret_cast<__nv_bfloat162*>(reinterpret_cast<char*>(Ah)+base+4)=p23h;
            *reinterpret_cast<__nv_bfloat162*>(reinterpret_cast<char*>(Al)+base)=p01l;
            *reinterpret_cast<__nv_bfloat162*>(reinterpret_cast<char*>(Al)+base+4)=p23l;
        }
        cp_pair(Bp,ch,tid);
        FPA(); __syncthreads();
        if(wid==0){ TFA();
            if(elect1()){
                mma3b(DQ,aAh,aAl,aBp,aBp+8192,ch>0);
                TCOMMIT(mbv[cc&1]);
            }
        }
        cc++;
    }
    WAITX; WAITX;
    TFA();
    epi_splitb(DQ+c0,b1+c0,XHb,XLb,m_r,c0,true);
    TFB(); FPA(); __syncthreads();

    // ======== 4 transformer layers ========
    for(int li=0;li<4;++li){
        for(int h=0;h<4;++h){
            if(h>0) WAITX;                 // O-mma(h-1)
            int base=8+(li*4+h)*3;
            cp_pair(R0f,base,tid);         // Bq pair
            cp_pair(R1f,base+1,tid);       // Bk pair
            cp_pair(R2f,base+2,tid);       // Bv pair
            FPA(); __syncthreads();
            if(wid==0){ TFA();
                if(elect1()){
                    mma3b(DQ,aXH,aXL,aR0,aR0+8192,false);
                    mma3b(DK,aXH,aXL,aR1,aR1+8192,false);
                    mma3b(DV,aXH,aXL,aR2,aR2+8192,false);
                    TCOMMIT(mbv[cc&1]);
                }
            }
            cc++;
            WAITX;
            TFA();
            epi_fullf(DQ+c0,bq+li*256+h*64+c0,R0f,m_r,c0);   // Q fp32 -> R0R1
            epi_fullf(DK+c0,bk+li*256+h*64+c0,R2f,m_r,c0);   // K fp32 -> R2R3
            TFB();
            __syncthreads();
            {   // scores per warp (= batch), fp32
                const int qi=l>>3,kj=l&7;
                float s0=0.f,s1=0.f;
#pragma unroll
                for(int d4=0;d4<64;d4+=4){
                    float4 kv=*reinterpret_cast<const float4*>(R2f+axAf(w*8+kj,d4));
                    float4 q0=*reinterpret_cast<const float4*>(R0f+axAf(w*8+qi,d4));
                    float4 q1=*reinterpret_cast<const float4*>(R0f+axAf(w*8+qi+4,d4));
                    s0+=q0.x*kv.x+q0.y*kv.y+q0.z*kv.z+q0.w*kv.w;
                    s1+=q1.x*kv.x+q1.y*kv.y+q1.z*kv.z+q1.w*kv.w;
                }
                s0*=SC_ATT;s1*=SC_ATT;
                float m0=s0,m1=s1;
#pragma unroll
                for(int o=1;o<8;o<<=1){
                    m0=fmaxf(m0,__shfl_xor_sync(0xffffffffu,m0,o));
                    m1=fmaxf(m1,__shfl_xor_sync(0xffffffffu,m1,o));
                }
                float e0=__expf(s0-m0),e1=__expf(s1-m1),t0=e0,t1=e1;
#pragma unroll
                for(int o=1;o<8;o<<=1){
                    t0+=__shfl_xor_sync(0xffffffffu,t0,o);
                    t1+=__shfl_xor_sync(0xffffffffu,t1,o);
                }
                float p0=e0/t0,p1=e1/t1;
                SP[w*64+l]=p0; SP[w*64+32+l]=p1;
                size_t ab=(size_t)(b0+w)*1024+li*256+h*64;
                attn_out[ab+l]=p0; attn_out[ab+32+l]=p1;
            }
            __syncthreads();               // all warps done with Q (R0R1)
            TFA();
            epi_fullf(DV+c0,bv+li*256+h*64+c0,R0f,m_r,c0);   // V fp32 -> R0R1
            TFB();
            __syncthreads();
            {   // ctx = P@V ; split bf16 pair into R2(hi)/R3(lo) (K dead)
                float a0[8],a1[8];
#pragma unroll
                for(int q2=0;q2<8;++q2){a0[q2]=0.f;a1[q2]=0.f;}
#pragma unroll
                for(int kk=0;kk<8;++kk){
                    float v0=R0f[axAf(w*8+kk,l)],v1=R0f[axAf(w*8+kk,l+32)];
#pragma unroll
                    for(int q2=0;q2<8;++q2){
                        float p=SP[w*64+q2*8+kk];
                        a0[q2]+=p*v0; a1[q2]+=p*v1;
                    }
                }
                __nv_bfloat16* CH=reinterpret_cast<__nv_bfloat16*>(R2f);
                __nv_bfloat16* CL=reinterpret_cast<__nv_bfloat16*>(R3f);
#pragma unroll
                for(int q2=0;q2<8;++q2){
                    int i0=axHb(w*8+q2,l), i1=axHb(w*8+q2,l+32);
                    sp2b(a0[q2],CH[i0],CL[i0]);
                    sp2b(a1[q2],CH[i1],CL[i1]);
                }
            }
            FPA(); __syncthreads();        // ctx visible; V dead
            cp_pair(R0f,56+li*4+h,tid);    // Wo pair
            FPA(); __syncthreads();
            if(wid==0){ TFA();
                if(elect1()){ mma3b(DO,aR2,aR3,aR0,aR0+8192,h>0); TCOMMIT(mbv[cc&1]); }
            }
            cc++;
        } // heads
        WAITX;
        TFA();
        epi_fullf(DO+c0,bo+li*64+c0,R0f,m_r,c0);    // Y fp32 -> R0R1
        TFB(); __syncthreads();
        ln_b(R0f,XHb,XLb,g1+li*64,be1+li*64,w,l);
        cp_pair(R2f,72+li*2,tid);                   // fW1 pair
        cp_pair(R3f,73+li*2,tid);                   // fW2 pair
        FPA(); __syncthreads();
        if(wid==0){ TFA();
            if(elect1()){ mma3b(DQ,aXH,aXL,aR2,aR2+8192,false); TCOMMIT(mbv[cc&1]); }
        }
        cc++;
        WAITX;
        TFA();
        epi_splitb(DQ+c0,fb1+li*64+c0,
                   reinterpret_cast<__nv_bfloat16*>(R0f),
                   reinterpret_cast<__nv_bfloat16*>(R1f),m_r,c0,true);  // h1 pair
        TFB(); FPA(); __syncthreads();
        if(wid==0){ TFA();
            if(elect1()){ mma3b(DK,aR0,aR1,aR3,aR3+8192,false); TCOMMIT(mbv[cc&1]); }
        }
        cc++;
        WAITX;
        TFA();
        epi_fullf(DK+c0,fb2+li*64+c0,R2f,m_r,c0);   // Y2 fp32 -> R2R3
        TFB(); __syncthreads();
        ln_b(R2f,XHb,XLb,g2+li*64,be2+li*64,w,l);
        FPA(); __syncthreads();
    } // layers

    // ======== cross attention ========
    for(int i=tid;i<1024;i+=NTM) SQI[i]=query[(size_t)(b0+(i>>6))*64+(i&63)];
    float ca0=0.f,ca1=0.f;
    for(int h=0;h<4;++h){
        cp_pair(R0f,80+h,tid);               // cWk pair
        cp_pair(R1f,84+h,tid);               // cWv pair
        cp_slicem(R2f,cWq+h*64,tid);         // cWq fp32 slice [64k][64n]
        cp_f4m(R3f,cWo+h*4096,1024,tid);     // cWo fp32 [64k][64n]
        FPA(); __syncthreads();
        if(wid==0){ TFA();
            if(elect1()){
                mma3b(DQ,aXH,aXL,aR0,aR0+8192,false);   // Kc
                mma3b(DK,aXH,aXL,aR1,aR1+8192,false);   // Vc
                TCOMMIT(mbv[cc&1]);
            }
        }
        cc++;
        for(int c=l;c<64;c+=32){             // Qc row per warp (fp32)
            float a=0.f;
#pragma unroll 8
            for(int k2=0;k2<64;++k2) a+=SQI[w*64+k2]*R2f[k2*64+c];
            QC[w*64+c]=a+cbq[h*64+c];
        }
        __syncwarp();
        WAITX;
        TFA();
        epi_fullf(DQ+c0,cbk+h*64+c0,R0f,m_r,c0);    // Kc fp32 -> R0R1
        TFB();
        __syncthreads();
        {   // cross scores 1x8 per warp
            const int j=l>>2,part=l&3;
            float sc=0.f;
#pragma unroll
            for(int d4=part*16;d4<part*16+16;d4+=4){
                float4 kv=*reinterpret_cast<const float4*>(R0f+axAf(w*8+j,d4));
                sc+=QC[w*64+d4]*kv.x+QC[w*64+d4+1]*kv.y+QC[w*64+d4+2]*kv.z+QC[w*64+d4+3]*kv.w;
            }
            sc+=__shfl_xor_sync(0xffffffffu,sc,1);
            sc+=__shfl_xor_sync(0xffffffffu,sc,2);
            sc*=SC_ATT;
            if(part==0) SP[w*64+j]=sc;
        }
        __syncthreads();                     // Kc dead
        TFA();
        epi_fullf(DK+c0,cbv+h*64+c0,R0f,m_r,c0);    // Vc fp32 -> R0R1
        TFB();
        __syncthreads();
        {
            float mx=-1e30f;
#pragma unroll
            for(int jj=0;jj<8;++jj) mx=fmaxf(mx,SP[w*64+jj]);
            float pe[8],ss=0.f;
#pragma unroll
            for(int jj=0;jj<8;++jj){pe[jj]=__expf(SP[w*64+jj]-mx);ss+=pe[jj];}
            float inv=1.f/ss;
            for(int c=l;c<64;c+=32){
                float a=0.f;
#pragma unroll
                for(int jj=0;jj<8;++jj) a+=pe[jj]*R0f[axAf(w*8+jj,c)];
                QC[w*64+c]=a*inv;            // ctx row replaces Qc
            }
            __syncwarp();
#pragma unroll 8
            for(int k2=0;k2<64;++k2){
                float cv=QC[w*64+k2];
                ca0+=cv*R3f[k2*64+l];
                ca1+=cv*R3f[k2*64+32+l];
            }
        }
        __syncthreads();
    }
    // ======== heads: color, sigma, out ========
    {
        float a0=fmaxf(ca0+cbo[l],0.f),a1=fmaxf(ca1+cbo[l+32],0.f);
#pragma unroll
        for(int cq=0;cq<3;++cq){
            float p=a0*Wc[l*3+cq]+a1*Wc[(l+32)*3+cq];
#pragma unroll
            for(int o=16;o>=1;o>>=1)p+=__shfl_xor_sync(0xffffffffu,p,o);
            if(l==0) out[(size_t)(b0+w)*3+cq]=p+bc[cq];
        }
        float m0=-1e30f,m1=-1e30f;
#pragma unroll
        for(int s2=0;s2<8;++s2){
            int i0=axHb(w*8+s2,l), i1=axHb(w*8+s2,l+32);
            m0=fmaxf(m0,(float)XHb[i0]+(float)XLb[i0]);
            m1=fmaxf(m1,(float)XHb[i1]+(float)XLb[i1]);
        }
        float p=m0*Ws[l]+m1*Ws[l+32];
#pragma unroll
        for(int o=16;o>=1;o>>=1)p+=__shfl_xor_sync(0xffffffffu,p,o);
        if(l==0) out[OFF_SIGMA+b0+w]=p+bs[0];
    }
    for(int i=tid;i<8192;i+=NTM){
        int ix=axHb(i>>6,i&63);
        out[OFF_OUT+(size_t)b0*512+i]=(float)XHb[ix]+(float)XLb[ix];
    }

    __syncthreads();
    if(wid==0)
        asm volatile("tcgen05.dealloc.cta_group::1.sync.aligned.b32 %0,%1;"::"r"(tb),"r"(256u));

    int allok=__syncthreads_and(ok?1:0);
    if(tid==0&&allok) atomicAdd(&g_ok,1);
#else
    (void)query;(void)latent;(void)b1;(void)bq;(void)bk;(void)bv;(void)bo;(void)fb1;(void)fb2;
    (void)g1;(void)be1;(void)g2;(void)be2;(void)cWq;(void)cbq;(void)cbk;(void)cbv;(void)cWo;
    (void)cbo;(void)Wc;(void)bc;(void)Ws;(void)bs;(void)out;
#endif
}

// =====================================================================
//  FFMA fallback — early-exits when MMA path fully succeeded
// =====================================================================
#define NTF 256
#define F_SX   0
#define F_SCTX 4096
#define F_ST   (4096+16384)
#define F_SW   (F_ST+12288)
#define F_SP   (F_SW+16384)
#define F_SQI  (F_SP+512)
#define F_SCA  (F_SQI+512)
#define F_SMEMF 50688

typedef unsigned long long ull;
__device__ __forceinline__ ull pk2(float lo,float hi){
    ull r; asm("mov.b64 %0,{%1,%2};":"=l"(r):"r"(__float_as_uint(lo)),"r"(__float_as_uint(hi))); return r;
}
__device__ __forceinline__ void fma2(ull &a,ull b,ull c){
    asm("fma.rn.f32x2 %0,%1,%2,%0;":"+l"(a):"l"(b),"l"(c));
}
__device__ __forceinline__ float2 upk(ull v){
    unsigned lo,hi; asm("mov.b64 {%0,%1},%2;":"=r"(lo),"=r"(hi):"l"(v));
    return make_float2(__uint_as_float(lo),__uint_as_float(hi));
}
__device__ __forceinline__ void cp_f4f(float* d,const float* s,int n4,int tid){
    for(int i=tid;i<n4;i+=NTF) reinterpret_cast<float4*>(d)[i]=reinterpret_cast<const float4*>(s)[i];
}
__device__ __forceinline__ void cp_slicef(float* d,const float* s,int tid){
    for(int i=tid;i<1024;i+=NTF){int r=i>>4,c=i&15;
        reinterpret_cast<float4*>(d)[i]=reinterpret_cast<const float4*>(s+r*256)[c];}
}
template<int K,int LDX>
__device__ __forceinline__ void gemm_accF(const float* X,const float* W,ull a01[4],ull a23[4],int c0,int rb){
#pragma unroll 8
    for(int k=0;k<K;++k){
        float4 wv=*reinterpret_cast<const float4*>(W+k*64+c0);
        ull w01=pk2(wv.x,wv.y),w23=pk2(wv.z,wv.w);
#pragma unroll
        for(int r=0;r<4;++r){
            float xv=X[(rb+r)*LDX+k];
            ull xx=pk2(xv,xv);
            fma2(a01[r],w01,xx); fma2(a23[r],w23,xx);
        }
    }
}
template<int K,int LDX,bool RELU>
__device__ __forceinline__ void gemm_blockF(const float* X,const float* W,const float* bias,float* Y,int tid){
    const int c0=(tid&15)*4, rb=(tid>>4)*4;
    ull a01[4]={0,0,0,0},a23[4]={0,0,0,0};
    gemm_accF<K,LDX>(X,W,a01,a23,c0,rb);
    float b0v=bias[c0],b1v=bias[c0+1],b2v=bias[c0+2],b3v=bias[c0+3];
#pragma unroll
    for(int r=0;r<4;++r){
        float2 v01=upk(a01[r]),v23=upk(a23[r]);
        float o0=v01.x+b0v,o1=v01.y+b1v,o2=v23.x+b2v,o3=v23.y+b3v;
        if(RELU){o0=fmaxf(o0,0.f);o1=fmaxf(o1,0.f);o2=fmaxf(o2,0.f);o3=fmaxf(o3,0.f);}
        *reinterpret_cast<float4*>(Y+(rb+r)*64+c0)=make_float4(o0,o1,o2,o3);
    }
}
__device__ __forceinline__ void ln_blockF(const float* Yd,float* Xs,const float* g,const float* be,int w,int l){
    float g0=g[l],g1v=g[l+32],e0=be[l],e1v=be[l+32];
#pragma unroll
    for(int i=0;i<8;++i){
        int r=w*8+i;
        float v0=Yd[r*64+l]+Xs[r*64+l];
        float v1=Yd[r*64+32+l]+Xs[r*64+32+l];
        float s=v0+v1;
#pragma unroll
        for(int o=16;o>=1;o>>=1)s+=__shfl_xor_sync(0xffffffffu,s,o);
        float m=s*(1.f/64.f),d0=v0-m,d1=v1-m,q=d0*d0+d1*d1;
#pragma unroll
        for(int o=16;o>=1;o>>=1)q+=__shfl_xor_sync(0xffffffffu,q,o);
        float inv=rsqrtf(q*(1.f/64.f)+LN_EPS);
        Xs[r*64+l]=d0*inv*g0+e0; Xs[r*64+32+l]=d1*inv*g1v+e1v;
    }
}

extern "C" __global__ void __launch_bounds__(256,1)
radiance_ffma(const float* __restrict__ query,const float* __restrict__ latent,
        const float* __restrict__ W1,const float* __restrict__ b1,
        const float* __restrict__ Wq,const float* __restrict__ bq,
        const float* __restrict__ Wk,const float* __restrict__ bk,
        const float* __restrict__ Wv,const float* __restrict__ bv,
        const float* __restrict__ Wo,const float* __restrict__ bo,
        const float* __restrict__ fW1,const float* __restrict__ fb1,
        const float* __restrict__ fW2,const float* __restrict__ fb2,
        const float* __restrict__ g1,const float* __restrict__ be1,
        const float* __restrict__ g2,const float* __restrict__ be2,
        const float* __restrict__ cWq,const float* __restrict__ cbq,
        const float* __restrict__ cWk,const float* __restrict__ cbk,
        const float* __restrict__ cWv,const float* __restrict__ cbv,
        const float* __restrict__ cWo,const float* __restrict__ cbo,
        const float* __restrict__ Wc,const float* __restrict__ bc,
        const float* __restrict__ Ws,const float* __restrict__ bs,
        float* __restrict__ out){
    if(*(volatile int*)&g_ok==MMA_GRID) return;
    extern __shared__ float smem[];
    float* SX=smem+F_SX; float* SCTX=smem+F_SCTX; float* ST=smem+F_ST;
    float* SW=smem+F_SW; float* SP=smem+F_SP; float* SQI=smem+F_SQI; float* SCA=smem+F_SCA;
    const int tid=threadIdx.x, w=tid>>5, l=tid&31, b0=blockIdx.x*8;
    float* attn_out=out+OFF_ATTN;

    {
        const int c0=(tid&15)*4, rb=(tid>>4)*4;
        ull a01[4]={0,0,0,0},a23[4]={0,0,0,0};
        for(int ch=0;ch<4;++ch){
            __syncthreads();
            cp_f4f(SW,W1+ch*8192,2048,tid);
            for(int i=tid;i<2048;i+=NTF){
                int r=i>>5,j=i&31;
                reinterpret_cast<float4*>(ST)[i]=
                    *reinterpret_cast<const float4*>(latent+(size_t)(b0*8+r)*512+ch*128+j*4);
            }
            __syncthreads();
            gemm_accF<128,128>(ST,SW,a01,a23,c0,rb);
        }
        float b0v=b1[c0],b1v=b1[c0+1],b2v=b1[c0+2],b3v=b1[c0+3];
#pragma unroll
        for(int r=0;r<4;++r){
            float2 v01=upk(a01[r]),v23=upk(a23[r]);
            *reinterpret_cast<float4*>(SX+(rb+r)*64+c0)=
                make_float4(fmaxf(v01.x+b0v,0.f),fmaxf(v01.y+b1v,0.f),
                            fmaxf(v23.x+b2v,0.f),fmaxf(v23.y+b3v,0.f));
        }
    }

    for(int li=0;li<4;++li){
        const float* Wq_i=Wq+li*16384; const float* Wk_i=Wk+li*16384;
        const float* Wv_i=Wv+li*16384;
        for(int h=0;h<4;++h){
            __syncthreads();
            cp_slicef(SW,Wq_i+h*64,tid);
            cp_slicef(SW+4096,Wk_i+h*64,tid);
            cp_slicef(SW+8192,Wv_i+h*64,tid);
            __syncthreads();
            gemm_blockF<64,64,false>(SX,SW,bq+li*256+h*64,ST,tid);
            gemm_blockF<64,64,false>(SX,SW+4096,bk+li*256+h*64,ST+4096,tid);
            gemm_blockF<64,64,false>(SX,SW+8192,bv+li*256+h*64,ST+8192,tid);
            __syncthreads();
            {
                const float* qB=ST+w*512; const float* kB=ST+4096+w*512; const float* vB=ST+8192+w*512;
                int qi=l>>3,kj=l&7;
                float s0=0.f,s1=0.f;
#pragma unroll 8
                for(int d=0;d<64;++d){
                    float kv=kB[kj*64+d];
                    s0+=qB[qi*64+d]*kv; s1+=qB[(qi+4)*64+d]*kv;
                }
                s0*=SC_ATT;s1*=SC_ATT;
                float m0=s0,m1=s1;
#pragma unroll
                for(int o=1;o<8;o<<=1){
                    m0=fmaxf(m0,__shfl_xor_sync(0xffffffffu,m0,o));
                    m1=fmaxf(m1,__shfl_xor_sync(0xffffffffu,m1,o));
                }
                float e0=expf(s0-m0),e1=expf(s1-m1),t0=e0,t1=e1;
#pragma unroll
                for(int o=1;o<8;o<<=1){
                    t0+=__shfl_xor_sync(0xffffffffu,t0,o);
                    t1+=__shfl_xor_sync(0xffffffffu,t1,o);
                }
                float p0=e0/t0,p1=e1/t1;
                SP[w*64+l]=p0; SP[w*64+32+l]=p1;
                size_t ab=(size_t)(b0+w)*1024+li*256+h*64;
                attn_out[ab+l]=p0; attn_out[ab+32+l]=p1;
                __syncwarp();
#pragma unroll
                for(int qq=0;qq<8;++qq){
                    float a0=0.f,a1=0.f;
#pragma unroll
                    for(int kk2=0;kk2<8;++kk2){
                        float p=SP[w*64+qq*8+kk2];
                        a0+=p*vB[kk2*64+l]; a1+=p*vB[kk2*64+32+l];
                    }
                    SCTX[(w*8+qq)*256+h*64+l]=a0;
                    SCTX[(w*8+qq)*256+h*64+32+l]=a1;
                }
            }
        }
        __syncthreads();
        cp_f4f(SW,Wo+li*16384,4096,tid);
        __syncthreads();
        gemm_blockF<256,256,false>(SCTX,SW,bo+li*64,ST,tid);
        __syncthreads();
        ln_blockF(ST,SX,g1+li*64,be1+li*64,w,l);
        __syncthreads();
        cp_f4f(SW,fW1+li*4096,1024,tid);
        cp_f4f(SW+4096,fW2+li*4096,1024,tid);
        __syncthreads();
        gemm_blockF<64,64,true>(SX,SW,fb1+li*64,ST+4096,tid);
        __syncthreads();
        gemm_blockF<64,64,false>(ST+4096,SW+4096,fb2+li*64,ST,tid);
        __syncthreads();
        ln_blockF(ST,SX,g2+li*64,be2+li*64,w,l);
    }

    for(int i=tid;i<512;i+=NTF)
        SQI[i]=query[(size_t)(b0+(i>>6))*64+(i&63)];

    for(int h=0;h<4;++h){
        __syncthreads();
        cp_slicef(SW,cWq+h*64,tid);
        cp_slicef(SW+4096,cWk+h*64,tid);
        cp_slicef(SW+8192,cWv+h*64,tid);
        __syncthreads();
        gemm_blockF<64,64,false>(SX,SW+4096,cbk+h*64,ST,tid);
        gemm_blockF<64,64,false>(SX,SW+8192,cbv+h*64,ST+4096,tid);
        for(int c=l;c<64;c+=32){
            float a=0.f;
#pragma unroll 8
            for(int k2=0;k2<64;++k2) a+=SQI[w*64+k2]*SW[k2*64+c];
            ST[8192+w*64+c]=a+cbq[h*64+c];
        }
        __syncthreads();
        {
            int j=l>>2,part=l&3;
            const float* qrow=ST+8192+w*64; const float* kB=ST+w*512;
            float sc=0.f;
#pragma unroll
            for(int d=part*16;d<part*16+16;++d) sc+=qrow[d]*kB[j*64+d];
            sc+=__shfl_xor_sync(0xffffffffu,sc,1);
            sc+=__shfl_xor_sync(0xffffffffu,sc,2);
            sc*=SC_ATT;
            if(part==0) SP[w*8+j]=sc;
            __syncwarp();
            float mx=-1e30f;
#pragma unroll
            for(int jj=0;jj<8;++jj) mx=fmaxf(mx,SP[w*8+jj]);
            float pe[8],ssum=0.f;
#pragma unroll
            for(int jj=0;jj<8;++jj){pe[jj]=expf(SP[w*8+jj]-mx);ssum+=pe[jj];}
            float inv=1.f/ssum;
            const float* vB=ST+4096+w*512;
            for(int c=l;c<64;c+=32){
                float a=0.f;
#pragma unroll
                for(int jj=0;jj<8;++jj) a+=pe[jj]*vB[jj*64+c];
                SCTX[(w*8)*256+h*64+c]=a*inv;
            }
        }
    }
    __syncthreads();
    cp_f4f(SW,cWo,4096,tid);
    __syncthreads();
    {
        const float* ctx=SCTX+w*2048;
        float a0=0.f,a1=0.f;
#pragma unroll 8
        for(int k2=0;k2<256;++k2){
            float cv=ctx[k2];
            a0+=cv*SW[k2*64+l]; a1+=cv*SW[k2*64+32+l];
        }
        a0=fmaxf(a0+cbo[l],0.f); a1=fmaxf(a1+cbo[l+32],0.f);
        SCA[w*64+l]=a0; SCA[w*64+32+l]=a1;
        __syncwarp();
#pragma unroll
        for(int cq=0;cq<3;++cq){
            float p=SCA[w*64+l]*Wc[l*3+cq]+SCA[w*64+32+l]*Wc[(l+32)*3+cq];
#pragma unroll
            for(int o=16;o>=1;o>>=1)p+=__shfl_xor_sync(0xffffffffu,p,o);
            if(l==0) out[(size_t)(b0+w)*3+cq]=p+bc[cq];
        }
        float m0=-1e30f,m1=-1e30f;
#pragma unroll
        for(int s2=0;s2<8;++s2){
            m0=fmaxf(m0,SX[(w*8+s2)*64+l]);
            m1=fmaxf(m1,SX[(w*8+s2)*64+32+l]);
        }
        float p=m0*Ws[l]+m1*Ws[l+32];
#pragma unroll
        for(int o=16;o>=1;o>>=1)p+=__shfl_xor_sync(0xffffffffu,p,o);
        if(l==0) out[OFF_SIGMA+b0+w]=p+bs[0];
    }
    for(int i=tid;i<4096;i+=NTF)
        out[OFF_OUT+(size_t)b0*512+i]=SX[i];
}

extern "C" void kernel_launch(void* const* d_in,const int* in_sizes,int n_in,
                              void* d_out,int out_size){
    (void)in_sizes;(void)n_in;(void)out_size;
    const float* query=(const float*)d_in[0];
    const float* latent=(const float*)d_in[1];
    const float* W1=(const float*)d_in[2];  const float* b1=(const float*)d_in[3];
    const float* Wq=(const float*)d_in[4];  const float* bq=(const float*)d_in[5];
    const float* Wk=(const float*)d_in[6];  const float* bk=(const float*)d_in[7];
    const float* Wv=(const float*)d_in[8];  const float* bv=(const float*)d_in[9];
    const float* Wo=(const float*)d_in[10]; const float* bo=(const float*)d_in[11];
    const float* fW1=(const float*)d_in[12];const float* fb1=(const float*)d_in[13];
    const float* fW2=(const float*)d_in[14];const float* fb2=(const float*)d_in[15];
    const float* g1=(const float*)d_in[16]; const float* be1=(const float*)d_in[17];
    const float* g2=(const float*)d_in[18]; const float* be2=(const float*)d_in[19];
    const float* cWq=(const float*)d_in[20];const float* cbq=(const float*)d_in[21];
    const float* cWk=(const float*)d_in[22];const float* cbk=(const float*)d_in[23];
    const float* cWv=(const float*)d_in[24];const float* cbv=(const float*)d_in[25];
    const float* cWo=(const float*)d_in[26];const float* cbo=(const float*)d_in[27];
    const float* Wc=(const float*)d_in[28]; const float* bc=(const float*)d_in[29];
    const float* Ws=(const float*)d_in[30]; const float* bs=(const float*)d_in[31];
    float* out=(float*)d_out;

    reset_kernel<<<1,1>>>();
    prep_kernel<<<(88*4096+255)/256,256>>>(W1,Wq,Wk,Wv,Wo,fW1,fW2,cWk,cWv);

    const int smem_mma=27664*sizeof(float);
    cudaFuncSetAttribute(radiance_mma,cudaFuncAttributeMaxDynamicSharedMemorySize,smem_mma);
    radiance_mma<<<MMA_GRID,512,smem_mma>>>(query,latent,b1,bq,bk,bv,bo,fb1,fb2,
        g1,be1,g2,be2,cWq,cbq,cbk,cbv,cWo,cbo,Wc,bc,Ws,bs,out);

    const int smem_ffma=F_SMEMF*sizeof(float);
    cudaFuncSetAttribute(radiance_ffma,cudaFuncAttributeMaxDynamicSharedMemorySize,smem_ffma);
    radiance_ffma<<<BB/8,256,smem_ffma>>>(query,latent,W1,b1,Wq,bq,Wk,bk,Wv,bv,Wo,bo,
        fW1,fb1,fW2,fb2,g1,be1,g2,be2,cWq,cbq,cWk,cbk,cWv,cbv,cWo,cbo,Wc,bc,Ws,bs,out);
}

// round 11
// speedup vs baseline: 5.6491x; 1.0278x over previous
#include <cuda_runtime.h>
#include <cuda_bf16.h>
#include <stdint.h>
#include <math.h>

#if defined(__CUDA_ARCH_FEAT_SM103_ALL) || defined(__CUDA_ARCH_FEAT_SM100_ALL) || defined(__CUDA_ARCH_FEAT_SM101_ALL)
#define HAS_TC 1
#else
#define HAS_TC 0
#endif

#define BB 32768
#define LN_EPS 1e-5f
#define SC_ATT 0.125f
#define OFF_SIGMA (3*BB)
#define OFF_OUT (OFF_SIGMA+BB)
#define OFF_ATTN (OFF_OUT+(size_t)BB*512)
#define MMA_GRID 2048

__device__ __nv_bfloat16 g_Bh[88*8192];   // per tile: 4096 hi then 4096 lo
__device__ int g_ok;

extern "C" __global__ void reset_kernel(){ g_ok = 0; }

// fp32 swizzled A-tile index ([128][64] fp32, 32KB)
__device__ __forceinline__ int axAf(int m,int k){return ((k>>5)<<12)|((m>>3)<<8)|((m&7)<<5)|((k&31)^((m&7)<<2));}
// bf16 tile element index ([R rows][64 k] bf16; atom = 8 rows x 128B)
__device__ __forceinline__ int axHb(int r,int k){
    int byte=(r&7)*128+k*2; byte^=((byte>>3)&0x70);
    return ((r>>3)<<9)+(byte>>1);
}
__device__ __forceinline__ void sp2b(float v,__nv_bfloat16&h,__nv_bfloat16&l){
    h=__float2bfloat16(v); l=__float2bfloat16(v-(float)h);
}

extern "C" __global__ void prep_kernel(const float* W1,const float* Wq,const float* Wk,const float* Wv,
        const float* Wo,const float* fW1,const float* fW2,const float* cWk,const float* cWv){
    int idx=blockIdx.x*256+threadIdx.x;
    if(idx>=88*4096)return;
    int tile=idx>>12,j=idx&4095,n=j>>6,k=j&63;
    float v;
    if(tile<8) v=W1[(tile*64+k)*64+n];
    else if(tile<56){int t=tile-8,lh=t/3,wch=t%3,li=lh>>2,h=lh&3;
        const float* W=(wch==0)?Wq:((wch==1)?Wk:Wv);
        v=W[li*16384+k*256+h*64+n];}
    else if(tile<72){int t=tile-56,li=t>>2,h=t&3; v=Wo[li*16384+(h*64+k)*64+n];}
    else if(tile<80){int t=tile-72,li=t>>1; v=((t&1)?fW2:fW1)[li*4096+k*64+n];}
    else if(tile<84) v=cWk[k*256+(tile-80)*64+n];
    else v=cWv[k*256+(tile-84)*64+n];
    __nv_bfloat16 h,l; sp2b(v,h,l);
    int ax=axHb(n,k);
    g_Bh[(size_t)tile*8192+ax]=h;
    g_Bh[(size_t)tile*8192+4096+ax]=l;
}

#if HAS_TC
#define NTM 512
#define IDESC 0x8100490u     // bf16, M=128, N=64, fp32 accum
// smem float offsets: regions of 4096 floats (16KB)
#define O_XH 0
#define O_XL 4096
#define O_R0 8192
#define O_R1 12288
#define O_R2 16384
#define O_R3 20480
#define O_SP 24576
#define O_QC 25600
#define O_SQI 26624
#define O_CTL 27648
#define SMEMF 27664

__device__ __forceinline__ uint32_t s2u(const void* p){
    uint32_t a; asm("{.reg .u64 t; cvta.to.shared.u64 t,%1; cvt.u32.u64 %0,t;}":"=r"(a):"l"(p)); return a;
}
__device__ __forceinline__ uint32_t elect1(){
    uint32_t r; asm volatile("{.reg .pred p; elect.sync _|p,0xFFFFFFFF; selp.b32 %0,1,0,p;}":"=r"(r)); return r;
}
__device__ __forceinline__ uint64_t sdesc(uint32_t a){
    const uint64_t b=(uint64_t(2)<<61)|(uint64_t(1)<<46)|(uint64_t(64)<<32)|(uint64_t(1)<<16);
    return b|((a>>4)&0x3FFFu);
}
__device__ __forceinline__ void mma1(uint32_t d,uint64_t ad,uint64_t bd,uint32_t en){
    asm volatile("{.reg .pred p; setp.ne.u32 p,%4,0;\n\t"
        "tcgen05.mma.cta_group::1.kind::f16 [%0],%1,%2,%3,{%5,%5,%5,%5},p;}"
        ::"r"(d),"l"(ad),"l"(bd),"r"(IDESC),"r"(en),"r"(0u):"memory");
}
// D[128,64] (+)= A[128,64]bf16 @ B[64,64]bf16^T ; K=16 per step, 4 steps
__device__ __forceinline__ void mma_k64b(uint32_t d,uint32_t a_s,uint32_t b_s,bool acc){
    uint64_t ad=sdesc(a_s),bd=sdesc(b_s);
#pragma unroll
    for(int s=0;s<4;++s)
        mma1(d,ad+(uint32_t)(s*2),bd+(uint32_t)(s*2),(acc||s>0)?1u:0u);
}
// 3xBF16: D = Ah@Bh + Al@Bh + Ah@Bl
__device__ __forceinline__ void mma3b(uint32_t d,uint32_t ah,uint32_t al,uint32_t bh,uint32_t bl,bool acc){
    mma_k64b(d,ah,bh,acc);
    mma_k64b(d,al,bh,true);
    mma_k64b(d,ah,bl,true);
}
#define TCOMMIT(mb) asm volatile("tcgen05.commit.cta_group::1.mbarrier::arrive::one.shared::cluster.b64 [%0];"::"r"(mb):"memory")
#define FPA() asm volatile("fence.proxy.async.shared::cta;":::"memory")
#define TFA() asm volatile("tcgen05.fence::after_thread_sync;":::"memory")
#define TFB() asm volatile("tcgen05.fence::before_thread_sync;":::"memory")

// sleeping bounded wait: HW TRYWAIT with suspend hint (no hot spin)
__device__ __forceinline__ bool mb_poll(uint32_t mb,uint32_t par){
    for(int i=0;i<40000;++i){
        uint32_t d;
        asm volatile("{.reg .pred P; mbarrier.try_wait.parity.acquire.cta.shared::cta.b64 P,[%1],%2,0x989680; selp.b32 %0,1,0,P;}"
            :"=r"(d):"r"(mb),"r"(par):"memory");
        if(d) return true;
    }
    return false;
}
__device__ __forceinline__ void ldtm16(uint32_t t,float* f){
    uint32_t r[16];
    asm volatile("tcgen05.ld.sync.aligned.32x32b.x16.b32 {%0,%1,%2,%3,%4,%5,%6,%7,%8,%9,%10,%11,%12,%13,%14,%15},[%16];"
        :"=r"(r[0]),"=r"(r[1]),"=r"(r[2]),"=r"(r[3]),"=r"(r[4]),"=r"(r[5]),"=r"(r[6]),"=r"(r[7]),
         "=r"(r[8]),"=r"(r[9]),"=r"(r[10]),"=r"(r[11]),"=r"(r[12]),"=r"(r[13]),"=r"(r[14]),"=r"(r[15])
        :"r"(t));
    asm volatile("tcgen05.wait::ld.sync.aligned;":::"memory");
#pragma unroll
    for(int i=0;i<16;++i) f[i]=__uint_as_float(r[i]);
}
// fp32 swizzled epilogue into 32KB buffer
__device__ __forceinline__ void epi_fullf(uint32_t t,const float* bias,float* X,int m_r,int c0){
    float r[16]; ldtm16(t,r);
#pragma unroll
    for(int i=0;i<16;i+=4){
        float4 v=make_float4(r[i]+bias[i],r[i+1]+bias[i+1],r[i+2]+bias[i+2],r[i+3]+bias[i+3]);
        *reinterpret_cast<float4*>(X+axAf(m_r,c0+i))=v;
    }
}
// split epilogue: bf16 hi/lo pairs into two 16KB tiles (packed bf16x2 stores)
__device__ __forceinline__ void epi_splitb(uint32_t t,const float* bias,
        __nv_bfloat16* Hb,__nv_bfloat16* Lb,int m_r,int c0,bool relu){
    float r[16]; ldtm16(t,r);
#pragma unroll
    for(int j=0;j<8;++j){
        float v0=r[2*j]+bias[2*j], v1=r[2*j+1]+bias[2*j+1];
        if(relu){v0=fmaxf(v0,0.f);v1=fmaxf(v1,0.f);}
        __nv_bfloat16 h0,l0,h1,l1;
        sp2b(v0,h0,l0); sp2b(v1,h1,l1);
        int k=c0+2*j;
        int byte=(m_r&7)*128+k*2; byte^=((byte>>3)&0x70);
        int base=((m_r>>3)<<10)+byte;
        __nv_bfloat162 hp; hp.x=h0; hp.y=h1;
        __nv_bfloat162 lp; lp.x=l0; lp.y=l1;
        *reinterpret_cast<__nv_bfloat162*>(reinterpret_cast<char*>(Hb)+base)=hp;
        *reinterpret_cast<__nv_bfloat162*>(reinterpret_cast<char*>(Lb)+base)=lp;
    }
}
__device__ __forceinline__ void cp_f4m(float* d,const float* s,int n4,int tid){
    for(int i=tid;i<n4;i+=NTM) reinterpret_cast<float4*>(d)[i]=reinterpret_cast<const float4*>(s)[i];
}
// copy one 16KB hi/lo bf16 tile pair
__device__ __forceinline__ void cp_pair(float* dst,int tile,int tid){
    const float4* s=reinterpret_cast<const float4*>(g_Bh+(size_t)tile*8192);
    for(int i=tid;i<1024;i+=NTM) reinterpret_cast<float4*>(dst)[i]=s[i];
}
__device__ __forceinline__ void cp_slicem(float* d,const float* s,int tid){
    for(int i=tid;i<1024;i+=NTM){int r=i>>4,c=i&15;
        reinterpret_cast<float4*>(d)[i]=reinterpret_cast<const float4*>(s+r*256)[c];}
}
// residual + LN; X persisted as bf16 hi/lo pair; Y fp32 swizzled
__device__ __forceinline__ void ln_b(const float* Y,__nv_bfloat16* XHb,__nv_bfloat16* XLb,
        const float* g,const float* be,int w,int l){
    float g0=g[l],g1v=g[l+32],e0=be[l],e1v=be[l+32];
#pragma unroll
    for(int i=0;i<8;++i){
        int r=w*8+i;
        int y0=axAf(r,l), y1=axAf(r,l+32);
        int b0i=axHb(r,l), b1i=axHb(r,l+32);
        float v0=Y[y0]+(float)XHb[b0i]+(float)XLb[b0i];
        float v1=Y[y1]+(float)XHb[b1i]+(float)XLb[b1i];
        float s=v0+v1;
#pragma unroll
        for(int o=16;o>=1;o>>=1)s+=__shfl_xor_sync(0xffffffffu,s,o);
        float m=s*(1.f/64.f),d0=v0-m,d1=v1-m,q=d0*d0+d1*d1;
#pragma unroll
        for(int o=16;o>=1;o>>=1)q+=__shfl_xor_sync(0xffffffffu,q,o);
        float inv=rsqrtf(q*(1.f/64.f)+LN_EPS);
        float a=d0*inv*g0+e0, b=d1*inv*g1v+e1v;
        sp2b(a,XHb[b0i],XLb[b0i]);
        sp2b(b,XHb[b1i],XLb[b1i]);
    }
}
// single-thread sleeping wait + block barrier release
#define WAITX do{ \
    if(tid==0){ if(SOK[0] && !mb_poll(mbv[wc&1],(uint32_t)((wc>>1)&1))) SOK[0]=0; } \
    __syncthreads(); \
    wc++; }while(0)
#endif

extern "C" __global__ void __launch_bounds__(512,2)
#if HAS_TC
__cluster_dims__(1,1,1)
#endif
radiance_mma(const float* __restrict__ query,const float* __restrict__ latent,
        const float* __restrict__ b1,const float* __restrict__ bq,const float* __restrict__ bk,
        const float* __restrict__ bv,const float* __restrict__ bo,const float* __restrict__ fb1,
        const float* __restrict__ fb2,const float* __restrict__ g1,const float* __restrict__ be1,
        const float* __restrict__ g2,const float* __restrict__ be2,const float* __restrict__ cWq,
        const float* __restrict__ cbq,const float* __restrict__ cbk,const float* __restrict__ cbv,
        const float* __restrict__ cWo,const float* __restrict__ cbo,const float* __restrict__ Wc,
        const float* __restrict__ bc,const float* __restrict__ Ws,const float* __restrict__ bs,
        float* __restrict__ out){
#if HAS_TC
    extern __shared__ float smem[];
    float* R0f=smem+O_R0; float* R1f=smem+O_R1; float* R2f=smem+O_R2; float* R3f=smem+O_R3;
    __nv_bfloat16* XHb=reinterpret_cast<__nv_bfloat16*>(smem+O_XH);
    __nv_bfloat16* XLb=reinterpret_cast<__nv_bfloat16*>(smem+O_XL);
    float* SP=smem+O_SP; float* QC=smem+O_QC; float* SQI=smem+O_SQI;
    volatile int* SOK=reinterpret_cast<volatile int*>(smem+O_CTL+6);
    const int tid=threadIdx.x,wid=tid>>5,l=tid&31,w=wid;
    const int b0=blockIdx.x*16;
    const int m_r=(wid&3)*32+l, c0=(wid>>2)*16;
    uint32_t sb=s2u(smem), ctl=sb+O_CTL*4;
    uint32_t mbv[2]={ctl+8,ctl+16};
    int cc=0, wc=0; (void)cc;

    if(tid==0){
        asm volatile("mbarrier.init.shared.b64 [%0],1;"::"r"(mbv[0]):"memory");
        asm volatile("mbarrier.init.shared.b64 [%0],1;"::"r"(mbv[1]):"memory");
        SOK[0]=1;
    }
    if(wid==0){
        asm volatile("tcgen05.alloc.cta_group::1.sync.aligned.shared::cta.b32 [%0],%1;"::"r"(ctl),"r"(256u):"memory");
        asm volatile("tcgen05.relinquish_alloc_permit.cta_group::1.sync.aligned;");
    }
    FPA(); __syncthreads();
    uint32_t tb; asm("ld.shared.b32 %0,[%1];":"=r"(tb):"r"(ctl));
    const uint32_t DQ=tb,DK=tb+64,DV=tb+128,DO=tb+192;
    const uint32_t aXH=sb+O_XH*4,aXL=sb+O_XL*4;
    const uint32_t aR0=sb+O_R0*4,aR1=sb+O_R1*4,aR2=sb+O_R2*4,aR3=sb+O_R3*4;
    float* attn_out=out+OFF_ATTN;

    // ======== stage0: X = relu(latent@W1+b1), K=512 in 8 chunks ========
    for(int ch=0;ch<8;++ch){
        if(ch>=2) WAITX;
        __nv_bfloat16* Ah=reinterpret_cast<__nv_bfloat16*>((ch&1)?R2f:R0f);
        __nv_bfloat16* Al=reinterpret_cast<__nv_bfloat16*>((ch&1)?R3f:R1f);
        float* Bp=(ch&1)?(smem+O_XL):(smem+O_XH);
        uint32_t aAh=(ch&1)?aR2:aR0, aAl=(ch&1)?aR3:aR1;
        uint32_t aBp=(ch&1)?aXL:aXH;
        for(int i=tid;i<2048;i+=NTM){
            int m=i>>4,k4=(i&15)<<2;
            float4 v=*reinterpret_cast<const float4*>(latent+(size_t)(b0*8+m)*512+ch*64+k4);
            __nv_bfloat16 h0,l0,h1,l1,h2,l2,h3,l3;
            sp2b(v.x,h0,l0); sp2b(v.y,h1,l1); sp2b(v.z,h2,l2); sp2b(v.w,h3,l3);
            int byte=(m&7)*128+k4*2; byte^=((byte>>3)&0x70);
            int base=((m>>3)<<10)+byte;
            __nv_bfloat162 p01h; p01h.x=h0; p01h.y=h1;
            __nv_bfloat162 p23h; p23h.x=h2; p23h.y=h3;
            __nv_bfloat162 p01l; p01l.x=l0; p01l.y=l1;
            __nv_bfloat162 p23l; p23l.x=l2; p23l.y=l3;
            *reinterpret_cast<__nv_bfloat162*>(reinterpret_cast<char*>(Ah)+base)=p01h;
            *reinterpret_cast<__nv_bfloat162*>(reinterpret_cast<char*>(Ah)+base+4)=p23h;
            *reinterpret_cast<__nv_bfloat162*>(reinterpret_cast<char*>(Al)+base)=p01l;
            *reinterpret_cast<__nv_bfloat162*>(reinterpret_cast<char*>(Al)+base+4)=p23l;
        }
        cp_pair(Bp,ch,tid);
        FPA(); __syncthreads();
        if(wid==0){ TFA();
            if(elect1()){
                mma3b(DQ,aAh,aAl,aBp,aBp+8192,ch>0);
                TCOMMIT(mbv[cc&1]);
            }
        }
        cc++;
    }
    WAITX; WAITX;
    TFA();
    epi_splitb(DQ+c0,b1+c0,XHb,XLb,m_r,c0,true);
    TFB(); FPA(); __syncthreads();

    // ======== 4 transformer layers ========
    for(int li=0;li<4;++li){
        for(int h=0;h<4;++h){
            if(h>0) WAITX;                 // O-mma(h-1)
            int base=8+(li*4+h)*3;
            cp_pair(R0f,base,tid);         // Bq pair
            cp_pair(R1f,base+1,tid);       // Bk pair
            cp_pair(R2f,base+2,tid);       // Bv pair
            FPA(); __syncthreads();
            if(wid==0){ TFA();
                if(elect1()){
                    mma3b(DQ,aXH,aXL,aR0,aR0+8192,false);
                    mma3b(DK,aXH,aXL,aR1,aR1+8192,false);
                    mma3b(DV,aXH,aXL,aR2,aR2+8192,false);
                    TCOMMIT(mbv[cc&1]);
                }
            }
            cc++;
            WAITX;
            TFA();
            epi_fullf(DQ+c0,bq+li*256+h*64+c0,R0f,m_r,c0);   // Q fp32 -> R0R1
            epi_fullf(DK+c0,bk+li*256+h*64+c0,R2f,m_r,c0);   // K fp32 -> R2R3
            TFB();
            __syncthreads();
            {   // scores per warp (= batch), fp32
                const int qi=l>>3,kj=l&7;
                float s0=0.f,s1=0.f;
#pragma unroll
                for(int d4=0;d4<64;d4+=4){
                    float4 kv=*reinterpret_cast<const float4*>(R2f+axAf(w*8+kj,d4));
                    float4 q0=*reinterpret_cast<const float4*>(R0f+axAf(w*8+qi,d4));
                    float4 q1=*reinterpret_cast<const float4*>(R0f+axAf(w*8+qi+4,d4));
                    s0+=q0.x*kv.x+q0.y*kv.y+q0.z*kv.z+q0.w*kv.w;
                    s1+=q1.x*kv.x+q1.y*kv.y+q1.z*kv.z+q1.w*kv.w;
                }
                s0*=SC_ATT;s1*=SC_ATT;
                float m0=s0,m1=s1;
#pragma unroll
                for(int o=1;o<8;o<<=1){
                    m0=fmaxf(m0,__shfl_xor_sync(0xffffffffu,m0,o));
                    m1=fmaxf(m1,__shfl_xor_sync(0xffffffffu,m1,o));
                }
                float e0=__expf(s0-m0),e1=__expf(s1-m1),t0=e0,t1=e1;
#pragma unroll
                for(int o=1;o<8;o<<=1){
                    t0+=__shfl_xor_sync(0xffffffffu,t0,o);
                    t1+=__shfl_xor_sync(0xffffffffu,t1,o);
                }
                float p0=e0/t0,p1=e1/t1;
                SP[w*64+l]=p0; SP[w*64+32+l]=p1;
                size_t ab=(size_t)(b0+w)*1024+li*256+h*64;
                attn_out[ab+l]=p0; attn_out[ab+32+l]=p1;
            }
            __syncthreads();               // all warps done with Q (R0R1)
            TFA();
            epi_fullf(DV+c0,bv+li*256+h*64+c0,R0f,m_r,c0);   // V fp32 -> R0R1
            TFB();
            __syncthreads();
            {   // ctx = P@V ; split bf16 pair into R2(hi)/R3(lo) (K dead)
                float a0[8],a1[8];
#pragma unroll
                for(int q2=0;q2<8;++q2){a0[q2]=0.f;a1[q2]=0.f;}
#pragma unroll
                for(int kk=0;kk<8;++kk){
                    float v0=R0f[axAf(w*8+kk,l)],v1=R0f[axAf(w*8+kk,l+32)];
#pragma unroll
                    for(int q2=0;q2<8;++q2){
                        float p=SP[w*64+q2*8+kk];
                        a0[q2]+=p*v0; a1[q2]+=p*v1;
                    }
                }
                __nv_bfloat16* CH=reinterpret_cast<__nv_bfloat16*>(R2f);
                __nv_bfloat16* CL=reinterpret_cast<__nv_bfloat16*>(R3f);
#pragma unroll
                for(int q2=0;q2<8;++q2){
                    int i0=axHb(w*8+q2,l), i1=axHb(w*8+q2,l+32);
                    sp2b(a0[q2],CH[i0],CL[i0]);
                    sp2b(a1[q2],CH[i1],CL[i1]);
                }
            }
            FPA(); __syncthreads();        // ctx visible; V dead
            cp_pair(R0f,56+li*4+h,tid);    // Wo pair
            FPA(); __syncthreads();
            if(wid==0){ TFA();
                if(elect1()){ mma3b(DO,aR2,aR3,aR0,aR0+8192,h>0); TCOMMIT(mbv[cc&1]); }
            }
            cc++;
        } // heads
        WAITX;
        TFA();
        epi_fullf(DO+c0,bo+li*64+c0,R0f,m_r,c0);    // Y fp32 -> R0R1
        TFB(); __syncthreads();
        ln_b(R0f,XHb,XLb,g1+li*64,be1+li*64,w,l);
        cp_pair(R2f,72+li*2,tid);                   // fW1 pair
        cp_pair(R3f,73+li*2,tid);                   // fW2 pair
        FPA(); __syncthreads();
        if(wid==0){ TFA();
            if(elect1()){ mma3b(DQ,aXH,aXL,aR2,aR2+8192,false); TCOMMIT(mbv[cc&1]); }
        }
        cc++;
        WAITX;
        TFA();
        epi_splitb(DQ+c0,fb1+li*64+c0,
                   reinterpret_cast<__nv_bfloat16*>(R0f),
                   reinterpret_cast<__nv_bfloat16*>(R1f),m_r,c0,true);  // h1 pair
        TFB(); FPA(); __syncthreads();
        if(wid==0){ TFA();
            if(elect1()){ mma3b(DK,aR0,aR1,aR3,aR3+8192,false); TCOMMIT(mbv[cc&1]); }
        }
        cc++;
        WAITX;
        TFA();
        epi_fullf(DK+c0,fb2+li*64+c0,R2f,m_r,c0);   // Y2 fp32 -> R2R3
        TFB(); __syncthreads();
        ln_b(R2f,XHb,XLb,g2+li*64,be2+li*64,w,l);
        FPA(); __syncthreads();
    } // layers

    // ======== cross attention ========
    for(int i=tid;i<1024;i+=NTM) SQI[i]=query[(size_t)(b0+(i>>6))*64+(i&63)];
    float ca0=0.f,ca1=0.f;
    for(int h=0;h<4;++h){
        cp_pair(R0f,80+h,tid);               // cWk pair
        cp_pair(R1f,84+h,tid);               // cWv pair
        cp_slicem(R2f,cWq+h*64,tid);         // cWq fp32 slice [64k][64n]
        cp_f4m(R3f,cWo+h*4096,1024,tid);     // cWo fp32 [64k][64n]
        FPA(); __syncthreads();
        if(wid==0){ TFA();
            if(elect1()){
                mma3b(DQ,aXH,aXL,aR0,aR0+8192,false);   // Kc
                mma3b(DK,aXH,aXL,aR1,aR1+8192,false);   // Vc
                TCOMMIT(mbv[cc&1]);
            }
        }
        cc++;
        for(int c=l;c<64;c+=32){             // Qc row per warp (fp32)
            float a=0.f;
#pragma unroll 8
            for(int k2=0;k2<64;++k2) a+=SQI[w*64+k2]*R2f[k2*64+c];
            QC[w*64+c]=a+cbq[h*64+c];
        }
        __syncwarp();
        WAITX;
        TFA();
        epi_fullf(DQ+c0,cbk+h*64+c0,R0f,m_r,c0);    // Kc fp32 -> R0R1
        TFB();
        __syncthreads();
        {   // cross scores 1x8 per warp
            const int j=l>>2,part=l&3;
            float sc=0.f;
#pragma unroll
            for(int d4=part*16;d4<part*16+16;d4+=4){
                float4 kv=*reinterpret_cast<const float4*>(R0f+axAf(w*8+j,d4));
                sc+=QC[w*64+d4]*kv.x+QC[w*64+d4+1]*kv.y+QC[w*64+d4+2]*kv.z+QC[w*64+d4+3]*kv.w;
            }
            sc+=__shfl_xor_sync(0xffffffffu,sc,1);
            sc+=__shfl_xor_sync(0xffffffffu,sc,2);
            sc*=SC_ATT;
            if(part==0) SP[w*64+j]=sc;
        }
        __syncthreads();                     // Kc dead
        TFA();
        epi_fullf(DK+c0,cbv+h*64+c0,R0f,m_r,c0);    // Vc fp32 -> R0R1
        TFB();
        __syncthreads();
        {
            float mx=-1e30f;
#pragma unroll
            for(int jj=0;jj<8;++jj) mx=fmaxf(mx,SP[w*64+jj]);
            float pe[8],ss=0.f;
#pragma unroll
            for(int jj=0;jj<8;++jj){pe[jj]=__expf(SP[w*64+jj]-mx);ss+=pe[jj];}
            float inv=1.f/ss;
            for(int c=l;c<64;c+=32){
                float a=0.f;
#pragma unroll
                for(int jj=0;jj<8;++jj) a+=pe[jj]*R0f[axAf(w*8+jj,c)];
                QC[w*64+c]=a*inv;            // ctx row replaces Qc
            }
            __syncwarp();
#pragma unroll 8
            for(int k2=0;k2<64;++k2){
                float cv=QC[w*64+k2];
                ca0+=cv*R3f[k2*64+l];
                ca1+=cv*R3f[k2*64+32+l];
            }
        }
        __syncthreads();
    }
    // ======== heads: color, sigma, out ========
    {
        float a0=fmaxf(ca0+cbo[l],0.f),a1=fmaxf(ca1+cbo[l+32],0.f);
#pragma unroll
        for(int cq=0;cq<3;++cq){
            float p=a0*Wc[l*3+cq]+a1*Wc[(l+32)*3+cq];
#pragma unroll
            for(int o=16;o>=1;o>>=1)p+=__shfl_xor_sync(0xffffffffu,p,o);
            if(l==0) out[(size_t)(b0+w)*3+cq]=p+bc[cq];
        }
        float m0=-1e30f,m1=-1e30f;
#pragma unroll
        for(int s2=0;s2<8;++s2){
            int i0=axHb(w*8+s2,l), i1=axHb(w*8+s2,l+32);
            m0=fmaxf(m0,(float)XHb[i0]+(float)XLb[i0]);
            m1=fmaxf(m1,(float)XHb[i1]+(float)XLb[i1]);
        }
        float p=m0*Ws[l]+m1*Ws[l+32];
#pragma unroll
        for(int o=16;o>=1;o>>=1)p+=__shfl_xor_sync(0xffffffffu,p,o);
        if(l==0) out[OFF_SIGMA+b0+w]=p+bs[0];
    }
    for(int i=tid;i<8192;i+=NTM){
        int ix=axHb(i>>6,i&63);
        out[OFF_OUT+(size_t)b0*512+i]=(float)XHb[ix]+(float)XLb[ix];
    }

    __syncthreads();
    if(wid==0)
        asm volatile("tcgen05.dealloc.cta_group::1.sync.aligned.b32 %0,%1;"::"r"(tb),"r"(256u));

    __syncthreads();
    if(tid==0&&SOK[0]) atomicAdd(&g_ok,1);
#else
    (void)query;(void)latent;(void)b1;(void)bq;(void)bk;(void)bv;(void)bo;(void)fb1;(void)fb2;
    (void)g1;(void)be1;(void)g2;(void)be2;(void)cWq;(void)cbq;(void)cbk;(void)cbv;(void)cWo;
    (void)cbo;(void)Wc;(void)bc;(void)Ws;(void)bs;(void)out;
#endif
}

// =====================================================================
//  FFMA fallback — early-exits when MMA path fully succeeded
// =====================================================================
#define NTF 256
#define F_SX   0
#define F_SCTX 4096
#define F_ST   (4096+16384)
#define F_SW   (F_ST+12288)
#define F_SP   (F_SW+16384)
#define F_SQI  (F_SP+512)
#define F_SCA  (F_SQI+512)
#define F_SMEMF 50688

typedef unsigned long long ull;
__device__ __forceinline__ ull pk2(float lo,float hi){
    ull r; asm("mov.b64 %0,{%1,%2};":"=l"(r):"r"(__float_as_uint(lo)),"r"(__float_as_uint(hi))); return r;
}
__device__ __forceinline__ void fma2(ull &a,ull b,ull c){
    asm("fma.rn.f32x2 %0,%1,%2,%0;":"+l"(a):"l"(b),"l"(c));
}
__device__ __forceinline__ float2 upk(ull v){
    unsigned lo,hi; asm("mov.b64 {%0,%1},%2;":"=r"(lo),"=r"(hi):"l"(v));
    return make_float2(__uint_as_float(lo),__uint_as_float(hi));
}
__device__ __forceinline__ void cp_f4f(float* d,const float* s,int n4,int tid){
    for(int i=tid;i<n4;i+=NTF) reinterpret_cast<float4*>(d)[i]=reinterpret_cast<const float4*>(s)[i];
}
__device__ __forceinline__ void cp_slicef(float* d,const float* s,int tid){
    for(int i=tid;i<1024;i+=NTF){int r=i>>4,c=i&15;
        reinterpret_cast<float4*>(d)[i]=reinterpret_cast<const float4*>(s+r*256)[c];}
}
template<int K,int LDX>
__device__ __forceinline__ void gemm_accF(const float* X,const float* W,ull a01[4],ull a23[4],int c0,int rb){
#pragma unroll 8
    for(int k=0;k<K;++k){
        float4 wv=*reinterpret_cast<const float4*>(W+k*64+c0);
        ull w01=pk2(wv.x,wv.y),w23=pk2(wv.z,wv.w);
#pragma unroll
        for(int r=0;r<4;++r){
            float xv=X[(rb+r)*LDX+k];
            ull xx=pk2(xv,xv);
            fma2(a01[r],w01,xx); fma2(a23[r],w23,xx);
        }
    }
}
template<int K,int LDX,bool RELU>
__device__ __forceinline__ void gemm_blockF(const float* X,const float* W,const float* bias,float* Y,int tid){
    const int c0=(tid&15)*4, rb=(tid>>4)*4;
    ull a01[4]={0,0,0,0},a23[4]={0,0,0,0};
    gemm_accF<K,LDX>(X,W,a01,a23,c0,rb);
    float b0v=bias[c0],b1v=bias[c0+1],b2v=bias[c0+2],b3v=bias[c0+3];
#pragma unroll
    for(int r=0;r<4;++r){
        float2 v01=upk(a01[r]),v23=upk(a23[r]);
        float o0=v01.x+b0v,o1=v01.y+b1v,o2=v23.x+b2v,o3=v23.y+b3v;
        if(RELU){o0=fmaxf(o0,0.f);o1=fmaxf(o1,0.f);o2=fmaxf(o2,0.f);o3=fmaxf(o3,0.f);}
        *reinterpret_cast<float4*>(Y+(rb+r)*64+c0)=make_float4(o0,o1,o2,o3);
    }
}
__device__ __forceinline__ void ln_blockF(const float* Yd,float* Xs,const float* g,const float* be,int w,int l){
    float g0=g[l],g1v=g[l+32],e0=be[l],e1v=be[l+32];
#pragma unroll
    for(int i=0;i<8;++i){
        int r=w*8+i;
        float v0=Yd[r*64+l]+Xs[r*64+l];
        float v1=Yd[r*64+32+l]+Xs[r*64+32+l];
        float s=v0+v1;
#pragma unroll
        for(int o=16;o>=1;o>>=1)s+=__shfl_xor_sync(0xffffffffu,s,o);
        float m=s*(1.f/64.f),d0=v0-m,d1=v1-m,q=d0*d0+d1*d1;
#pragma unroll
        for(int o=16;o>=1;o>>=1)q+=__shfl_xor_sync(0xffffffffu,q,o);
        float inv=rsqrtf(q*(1.f/64.f)+LN_EPS);
        Xs[r*64+l]=d0*inv*g0+e0; Xs[r*64+32+l]=d1*inv*g1v+e1v;
    }
}

extern "C" __global__ void __launch_bounds__(256,1)
radiance_ffma(const float* __restrict__ query,const float* __restrict__ latent,
        const float* __restrict__ W1,const float* __restrict__ b1,
        const float* __restrict__ Wq,const float* __restrict__ bq,
        const float* __restrict__ Wk,const float* __restrict__ bk,
        const float* __restrict__ Wv,const float* __restrict__ bv,
        const float* __restrict__ Wo,const float* __restrict__ bo,
        const float* __restrict__ fW1,const float* __restrict__ fb1,
        const float* __restrict__ fW2,const float* __restrict__ fb2,
        const float* __restrict__ g1,const float* __restrict__ be1,
        const float* __restrict__ g2,const float* __restrict__ be2,
        const float* __restrict__ cWq,const float* __restrict__ cbq,
        const float* __restrict__ cWk,const float* __restrict__ cbk,
        const float* __restrict__ cWv,const float* __restrict__ cbv,
        const float* __restrict__ cWo,const float* __restrict__ cbo,
        const float* __restrict__ Wc,const float* __restrict__ bc,
        const float* __restrict__ Ws,const float* __restrict__ bs,
        float* __restrict__ out){
    if(*(volatile int*)&g_ok==MMA_GRID) return;
    extern __shared__ float smem[];
    float* SX=smem+F_SX; float* SCTX=smem+F_SCTX; float* ST=smem+F_ST;
    float* SW=smem+F_SW; float* SP=smem+F_SP; float* SQI=smem+F_SQI; float* SCA=smem+F_SCA;
    const int tid=threadIdx.x, w=tid>>5, l=tid&31, b0=blockIdx.x*8;
    float* attn_out=out+OFF_ATTN;

    {
        const int c0=(tid&15)*4, rb=(tid>>4)*4;
        ull a01[4]={0,0,0,0},a23[4]={0,0,0,0};
        for(int ch=0;ch<4;++ch){
            __syncthreads();
            cp_f4f(SW,W1+ch*8192,2048,tid);
            for(int i=tid;i<2048;i+=NTF){
                int r=i>>5,j=i&31;
                reinterpret_cast<float4*>(ST)[i]=
                    *reinterpret_cast<const float4*>(latent+(size_t)(b0*8+r)*512+ch*128+j*4);
            }
            __syncthreads();
            gemm_accF<128,128>(ST,SW,a01,a23,c0,rb);
        }
        float b0v=b1[c0],b1v=b1[c0+1],b2v=b1[c0+2],b3v=b1[c0+3];
#pragma unroll
        for(int r=0;r<4;++r){
            float2 v01=upk(a01[r]),v23=upk(a23[r]);
            *reinterpret_cast<float4*>(SX+(rb+r)*64+c0)=
                make_float4(fmaxf(v01.x+b0v,0.f),fmaxf(v01.y+b1v,0.f),
                            fmaxf(v23.x+b2v,0.f),fmaxf(v23.y+b3v,0.f));
        }
    }

    for(int li=0;li<4;++li){
        const float* Wq_i=Wq+li*16384; const float* Wk_i=Wk+li*16384;
        const float* Wv_i=Wv+li*16384;
        for(int h=0;h<4;++h){
            __syncthreads();
            cp_slicef(SW,Wq_i+h*64,tid);
            cp_slicef(SW+4096,Wk_i+h*64,tid);
            cp_slicef(SW+8192,Wv_i+h*64,tid);
            __syncthreads();
            gemm_blockF<64,64,false>(SX,SW,bq+li*256+h*64,ST,tid);
            gemm_blockF<64,64,false>(SX,SW+4096,bk+li*256+h*64,ST+4096,tid);
            gemm_blockF<64,64,false>(SX,SW+8192,bv+li*256+h*64,ST+8192,tid);
            __syncthreads();
            {
                const float* qB=ST+w*512; const float* kB=ST+4096+w*512; const float* vB=ST+8192+w*512;
                int qi=l>>3,kj=l&7;
                float s0=0.f,s1=0.f;
#pragma unroll 8
                for(int d=0;d<64;++d){
                    float kv=kB[kj*64+d];
                    s0+=qB[qi*64+d]*kv; s1+=qB[(qi+4)*64+d]*kv;
                }
                s0*=SC_ATT;s1*=SC_ATT;
                float m0=s0,m1=s1;
#pragma unroll
                for(int o=1;o<8;o<<=1){
                    m0=fmaxf(m0,__shfl_xor_sync(0xffffffffu,m0,o));
                    m1=fmaxf(m1,__shfl_xor_sync(0xffffffffu,m1,o));
                }
                float e0=expf(s0-m0),e1=expf(s1-m1),t0=e0,t1=e1;
#pragma unroll
                for(int o=1;o<8;o<<=1){
                    t0+=__shfl_xor_sync(0xffffffffu,t0,o);
                    t1+=__shfl_xor_sync(0xffffffffu,t1,o);
                }
                float p0=e0/t0,p1=e1/t1;
                SP[w*64+l]=p0; SP[w*64+32+l]=p1;
                size_t ab=(size_t)(b0+w)*1024+li*256+h*64;
                attn_out[ab+l]=p0; attn_out[ab+32+l]=p1;
                __syncwarp();
#pragma unroll
                for(int qq=0;qq<8;++qq){
                    float a0=0.f,a1=0.f;
#pragma unroll
                    for(int kk2=0;kk2<8;++kk2){
                        float p=SP[w*64+qq*8+kk2];
                        a0+=p*vB[kk2*64+l]; a1+=p*vB[kk2*64+32+l];
                    }
                    SCTX[(w*8+qq)*256+h*64+l]=a0;
                    SCTX[(w*8+qq)*256+h*64+32+l]=a1;
                }
            }
        }
        __syncthreads();
        cp_f4f(SW,Wo+li*16384,4096,tid);
        __syncthreads();
        gemm_blockF<256,256,false>(SCTX,SW,bo+li*64,ST,tid);
        __syncthreads();
        ln_blockF(ST,SX,g1+li*64,be1+li*64,w,l);
        __syncthreads();
        cp_f4f(SW,fW1+li*4096,1024,tid);
        cp_f4f(SW+4096,fW2+li*4096,1024,tid);
        __syncthreads();
        gemm_blockF<64,64,true>(SX,SW,fb1+li*64,ST+4096,tid);
        __syncthreads();
        gemm_blockF<64,64,false>(ST+4096,SW+4096,fb2+li*64,ST,tid);
        __syncthreads();
        ln_blockF(ST,SX,g2+li*64,be2+li*64,w,l);
    }

    for(int i=tid;i<512;i+=NTF)
        SQI[i]=query[(size_t)(b0+(i>>6))*64+(i&63)];

    for(int h=0;h<4;++h){
        __syncthreads();
        cp_slicef(SW,cWq+h*64,tid);
        cp_slicef(SW+4096,cWk+h*64,tid);
        cp_slicef(SW+8192,cWv+h*64,tid);
        __syncthreads();
        gemm_blockF<64,64,false>(SX,SW+4096,cbk+h*64,ST,tid);
        gemm_blockF<64,64,false>(SX,SW+8192,cbv+h*64,ST+4096,tid);
        for(int c=l;c<64;c+=32){
            float a=0.f;
#pragma unroll 8
            for(int k2=0;k2<64;++k2) a+=SQI[w*64+k2]*SW[k2*64+c];
            ST[8192+w*64+c]=a+cbq[h*64+c];
        }
        __syncthreads();
        {
            int j=l>>2,part=l&3;
            const float* qrow=ST+8192+w*64; const float* kB=ST+w*512;
            float sc=0.f;
#pragma unroll
            for(int d=part*16;d<part*16+16;++d) sc+=qrow[d]*kB[j*64+d];
            sc+=__shfl_xor_sync(0xffffffffu,sc,1);
            sc+=__shfl_xor_sync(0xffffffffu,sc,2);
            sc*=SC_ATT;
            if(part==0) SP[w*8+j]=sc;
            __syncwarp();
            float mx=-1e30f;
#pragma unroll
            for(int jj=0;jj<8;++jj) mx=fmaxf(mx,SP[w*8+jj]);
            float pe[8],ssum=0.f;
#pragma unroll
            for(int jj=0;jj<8;++jj){pe[jj]=expf(SP[w*8+jj]-mx);ssum+=pe[jj];}
            float inv=1.f/ssum;
            const float* vB=ST+4096+w*512;
            for(int c=l;c<64;c+=32){
                float a=0.f;
#pragma unroll
                for(int jj=0;jj<8;++jj) a+=pe[jj]*vB[jj*64+c];
                SCTX[(w*8)*256+h*64+c]=a*inv;
            }
        }
    }
    __syncthreads();
    cp_f4f(SW,cWo,4096,tid);
    __syncthreads();
    {
        const float* ctx=SCTX+w*2048;
        float a0=0.f,a1=0.f;
#pragma unroll 8
        for(int k2=0;k2<256;++k2){
            float cv=ctx[k2];
            a0+=cv*SW[k2*64+l]; a1+=cv*SW[k2*64+32+l];
        }
        a0=fmaxf(a0+cbo[l],0.f); a1=fmaxf(a1+cbo[l+32],0.f);
        SCA[w*64+l]=a0; SCA[w*64+32+l]=a1;
        __syncwarp();
#pragma unroll
        for(int cq=0;cq<3;++cq){
            float p=SCA[w*64+l]*Wc[l*3+cq]+SCA[w*64+32+l]*Wc[(l+32)*3+cq];
#pragma unroll
            for(int o=16;o>=1;o>>=1)p+=__shfl_xor_sync(0xffffffffu,p,o);
            if(l==0) out[(size_t)(b0+w)*3+cq]=p+bc[cq];
        }
        float m0=-1e30f,m1=-1e30f;
#pragma unroll
        for(int s2=0;s2<8;++s2){
            m0=fmaxf(m0,SX[(w*8+s2)*64+l]);
            m1=fmaxf(m1,SX[(w*8+s2)*64+32+l]);
        }
        float p=m0*Ws[l]+m1*Ws[l+32];
#pragma unroll
        for(int o=16;o>=1;o>>=1)p+=__shfl_xor_sync(0xffffffffu,p,o);
        if(l==0) out[OFF_SIGMA+b0+w]=p+bs[0];
    }
    for(int i=tid;i<4096;i+=NTF)
        out[OFF_OUT+(size_t)b0*512+i]=SX[i];
}

extern "C" void kernel_launch(void* const* d_in,const int* in_sizes,int n_in,
                              void* d_out,int out_size){
    (void)in_sizes;(void)n_in;(void)out_size;
    const float* query=(const float*)d_in[0];
    const float* latent=(const float*)d_in[1];
    const float* W1=(const float*)d_in[2];  const float* b1=(const float*)d_in[3];
    const float* Wq=(const float*)d_in[4];  const float* bq=(const float*)d_in[5];
    const float* Wk=(const float*)d_in[6];  const float* bk=(const float*)d_in[7];
    const float* Wv=(const float*)d_in[8];  const float* bv=(const float*)d_in[9];
    const float* Wo=(const float*)d_in[10]; const float* bo=(const float*)d_in[11];
    const float* fW1=(const float*)d_in[12];const float* fb1=(const float*)d_in[13];
    const float* fW2=(const float*)d_in[14];const float* fb2=(const float*)d_in[15];
    const float* g1=(const float*)d_in[16]; const float* be1=(const float*)d_in[17];
    const float* g2=(const float*)d_in[18]; const float* be2=(const float*)d_in[19];
    const float* cWq=(const float*)d_in[20];const float* cbq=(const float*)d_in[21];
    const float* cWk=(const float*)d_in[22];const float* cbk=(const float*)d_in[23];
    const float* cWv=(const float*)d_in[24];const float* cbv=(const float*)d_in[25];
    const float* cWo=(const float*)d_in[26];const float* cbo=(const float*)d_in[27];
    const float* Wc=(const float*)d_in[28]; const float* bc=(const float*)d_in[29];
    const float* Ws=(const float*)d_in[30]; const float* bs=(const float*)d_in[31];
    float* out=(float*)d_out;

    reset_kernel<<<1,1>>>();
    prep_kernel<<<(88*4096+255)/256,256>>>(W1,Wq,Wk,Wv,Wo,fW1,fW2,cWk,cWv);

    const int smem_mma=27664*sizeof(float);
    cudaFuncSetAttribute(radiance_mma,cudaFuncAttributeMaxDynamicSharedMemorySize,smem_mma);
    radiance_mma<<<MMA_GRID,512,smem_mma>>>(query,latent,b1,bq,bk,bv,bo,fb1,fb2,
        g1,be1,g2,be2,cWq,cbq,cbk,cbv,cWo,cbo,Wc,bc,Ws,bs,out);

    const int smem_ffma=F_SMEMF*sizeof(float);
    cudaFuncSetAttribute(radiance_ffma,cudaFuncAttributeMaxDynamicSharedMemorySize,smem_ffma);
    radiance_ffma<<<BB/8,256,smem_ffma>>>(query,latent,W1,b1,Wq,bq,Wk,bk,Wv,bv,Wo,bo,
        fW1,fb1,fW2,fb2,g1,be1,g2,be2,cWq,cbq,cWk,cbk,cWv,cbv,cWo,cbo,Wc,bc,Ws,bs,out);
}